// round 1
// baseline (speedup 1.0000x reference)
#include <cuda_runtime.h>
#include <math.h>

#define N 8192
#define D 256
#define CLAMP_MIN 1e-30f

// ---- scratch (no allocations allowed) ----
__device__ float g_y[(size_t)N * D];   // normalized, then centered, vectors
__device__ float g_colsum[D];
__device__ float g_n2[N];              // ||z_i||^2 after centering
__device__ float g_rowmax[N];          // max_j 1/dist  (float bits, monotone for positives)

// ---- init: zero accumulators (must re-run every graph replay) ----
__global__ void k_init() {
    int idx = blockIdx.x * 256 + threadIdx.x;
    if (idx < N) g_rowmax[idx] = 0.0f;
    if (idx < D) g_colsum[idx] = 0.0f;
}

// ---- row L2-normalize: one block per row, 256 threads ----
__global__ void k_normalize(const float* __restrict__ x) {
    int row = blockIdx.x;
    int t = threadIdx.x;
    float v = x[(size_t)row * D + t];
    float s = v * v;
    __shared__ float sm[8];
    #pragma unroll
    for (int o = 16; o; o >>= 1) s += __shfl_xor_sync(0xffffffffu, s, o);
    if ((t & 31) == 0) sm[t >> 5] = s;
    __syncthreads();
    if (t < 8) {
        float a = sm[t];
        #pragma unroll
        for (int o = 4; o; o >>= 1) a += __shfl_xor_sync(0xffu, a, o);
        if (t == 0) sm[0] = a;
    }
    __syncthreads();
    float inv = 1.0f / sqrtf(sm[0]);
    g_y[(size_t)row * D + t] = v * inv;
}

// ---- column sums of normalized matrix: 32 blocks x 256 rows each ----
__global__ void k_colsum() {
    int t = threadIdx.x;
    int r0 = blockIdx.x * (N / 32);
    float s = 0.0f;
    for (int r = 0; r < N / 32; ++r) s += g_y[(size_t)(r0 + r) * D + t];
    atomicAdd(&g_colsum[t], s);
}

// ---- subtract column mean in-place; compute centered row sq-norms ----
__global__ void k_center() {
    int row = blockIdx.x;
    int t = threadIdx.x;
    float z = g_y[(size_t)row * D + t] - g_colsum[t] * (1.0f / (float)N);
    g_y[(size_t)row * D + t] = z;
    float s = z * z;
    __shared__ float sm[8];
    #pragma unroll
    for (int o = 16; o; o >>= 1) s += __shfl_xor_sync(0xffffffffu, s, o);
    if ((t & 31) == 0) sm[t >> 5] = s;
    __syncthreads();
    if (t < 8) {
        float a = sm[t];
        #pragma unroll
        for (int o = 4; o; o >>= 1) a += __shfl_xor_sync(0xffu, a, o);
        if (t == 0) g_n2[row] = a;
    }
}

// ---- fused Gram + distance + rowmax(1/dist) ----
// 128x128 output tile per block, 256 threads, 8x8 register micro-tile, BK=32.
__global__ __launch_bounds__(256) void k_dist() {
    __shared__ float As[32][132];   // [k][i], pad 132 keeps 16B alignment, 4-way STS conflict only
    __shared__ float Bs[32][132];   // [k][j]
    __shared__ float sNi[128], sNj[128];

    int t  = threadIdx.x;
    int tx = t & 15;
    int ty = t >> 4;
    int i0 = blockIdx.y * 128;
    int j0 = blockIdx.x * 128;

    if (t < 128) sNi[t] = g_n2[i0 + t];
    else         sNj[t - 128] = g_n2[j0 + t - 128];

    float acc[8][8];
    #pragma unroll
    for (int m = 0; m < 8; ++m)
        #pragma unroll
        for (int n = 0; n < 8; ++n) acc[m][n] = 0.0f;

    int lc  = t & 31;   // k within chunk
    int lr0 = t >> 5;   // row sub-index

    for (int k0 = 0; k0 < D; k0 += 32) {
        #pragma unroll
        for (int l = 0; l < 16; ++l) {
            int r = l * 8 + lr0;
            As[lc][r] = g_y[(size_t)(i0 + r) * D + k0 + lc];
            Bs[lc][r] = g_y[(size_t)(j0 + r) * D + k0 + lc];
        }
        __syncthreads();
        #pragma unroll
        for (int k = 0; k < 32; ++k) {
            float a[8], b[8];
            #pragma unroll
            for (int m = 0; m < 8; ++m) a[m] = As[k][ty * 8 + m];
            #pragma unroll
            for (int n = 0; n < 8; ++n) b[n] = Bs[k][tx * 8 + n];
            #pragma unroll
            for (int m = 0; m < 8; ++m)
                #pragma unroll
                for (int n = 0; n < 8; ++n)
                    acc[m][n] = fmaf(a[m], b[n], acc[m][n]);
        }
        __syncthreads();
    }

    // epilogue: dist, diag fix, 1/dist, row max
    float rmax[8];
    #pragma unroll
    for (int m = 0; m < 8; ++m) rmax[m] = 0.0f;

    #pragma unroll
    for (int m = 0; m < 8; ++m) {
        int i = i0 + ty * 8 + m;
        float ni = sNi[ty * 8 + m];
        #pragma unroll
        for (int n = 0; n < 8; ++n) {
            int j = j0 + tx * 8 + n;
            float d2 = ni + sNj[tx * 8 + n] - 2.0f * acc[m][n];
            float dist = sqrtf(fmaxf(d2, CLAMP_MIN));
            if (i == j) dist = dist + 10.0f * (1.0f - dist);  // diag -> ~10
            rmax[m] = fmaxf(rmax[m], 1.0f / dist);
        }
    }

    // reduce across tx (16-lane groups share the same rows), then 1 atomic per row
    #pragma unroll
    for (int m = 0; m < 8; ++m) {
        float v = rmax[m];
        #pragma unroll
        for (int o = 8; o; o >>= 1) v = fmaxf(v, __shfl_xor_sync(0xffffffffu, v, o));
        if (tx == 0)
            atomicMax((int*)&g_rowmax[i0 + ty * 8 + m], __float_as_int(v));
    }
}

// ---- final mean ----
__global__ void k_final(float* __restrict__ out) {
    int t = threadIdx.x;
    float s = 0.0f;
    for (int i = t; i < N; i += 256) s += g_rowmax[i];
    __shared__ float sm[8];
    #pragma unroll
    for (int o = 16; o; o >>= 1) s += __shfl_xor_sync(0xffffffffu, s, o);
    if ((t & 31) == 0) sm[t >> 5] = s;
    __syncthreads();
    if (t < 8) {
        float a = sm[t];
        #pragma unroll
        for (int o = 4; o; o >>= 1) a += __shfl_xor_sync(0xffu, a, o);
        if (t == 0) out[0] = a * (1.0f / (float)N);
    }
}

extern "C" void kernel_launch(void* const* d_in, const int* in_sizes, int n_in,
                              void* d_out, int out_size) {
    const float* x = (const float*)d_in[0];
    float* out = (float*)d_out;

    k_init<<<32, 256>>>();
    k_normalize<<<N, 256>>>(x);
    k_colsum<<<32, 256>>>();
    k_center<<<N, 256>>>();
    dim3 grid(64, 64);
    k_dist<<<grid, 256>>>();
    k_final<<<1, 256>>>(out);
}

// round 2
// speedup vs baseline: 1.7622x; 1.7622x over previous
#include <cuda_runtime.h>
#include <math.h>

#define N 8192
#define D 256
#define CLAMP_MIN 1e-30f

// ---- scratch (no allocations allowed) ----
__device__ float g_y[(size_t)N * D];   // normalized, then centered, vectors
__device__ float g_colsum[D];
__device__ float g_n2[N];              // ||z_i||^2 after centering
__device__ float g_rowmax[N];          // max_j 1/dist  (float bits, monotone for positives)

// ---- init: zero accumulators (must re-run every graph replay) ----
__global__ void k_init() {
    int idx = blockIdx.x * 256 + threadIdx.x;
    if (idx < N) g_rowmax[idx] = 0.0f;
    if (idx < D) g_colsum[idx] = 0.0f;
}

// ---- row L2-normalize: one block per row, 256 threads ----
__global__ void k_normalize(const float* __restrict__ x) {
    int row = blockIdx.x;
    int t = threadIdx.x;
    float v = x[(size_t)row * D + t];
    float s = v * v;
    __shared__ float sm[8];
    #pragma unroll
    for (int o = 16; o; o >>= 1) s += __shfl_xor_sync(0xffffffffu, s, o);
    if ((t & 31) == 0) sm[t >> 5] = s;
    __syncthreads();
    if (t < 8) {
        float a = sm[t];
        #pragma unroll
        for (int o = 4; o; o >>= 1) a += __shfl_xor_sync(0xffu, a, o);
        if (t == 0) sm[0] = a;
    }
    __syncthreads();
    float inv = 1.0f / sqrtf(sm[0]);
    g_y[(size_t)row * D + t] = v * inv;
}

// ---- column sums of normalized matrix: 32 blocks x 256 rows each ----
__global__ void k_colsum() {
    int t = threadIdx.x;
    int r0 = blockIdx.x * (N / 32);
    float s = 0.0f;
    for (int r = 0; r < N / 32; ++r) s += g_y[(size_t)(r0 + r) * D + t];
    atomicAdd(&g_colsum[t], s);
}

// ---- subtract column mean in-place; compute centered row sq-norms ----
__global__ void k_center() {
    int row = blockIdx.x;
    int t = threadIdx.x;
    float z = g_y[(size_t)row * D + t] - g_colsum[t] * (1.0f / (float)N);
    g_y[(size_t)row * D + t] = z;
    float s = z * z;
    __shared__ float sm[8];
    #pragma unroll
    for (int o = 16; o; o >>= 1) s += __shfl_xor_sync(0xffffffffu, s, o);
    if ((t & 31) == 0) sm[t >> 5] = s;
    __syncthreads();
    if (t < 8) {
        float a = sm[t];
        #pragma unroll
        for (int o = 4; o; o >>= 1) a += __shfl_xor_sync(0xffu, a, o);
        if (t == 0) g_n2[row] = a;
    }
}

// ---- fused Gram + distance + rowmax(1/dist), UPPER-TRIANGLE ONLY ----
// 128x128 output tile per block, 256 threads, 8x8 register micro-tile, BK=32.
// Off-diagonal tiles also emit a column-max that serves the mirrored tile.
__global__ __launch_bounds__(256) void k_dist() {
    int bi = blockIdx.y;   // row tile
    int bj = blockIdx.x;   // col tile
    if (bj < bi) return;   // symmetry: skip lower triangle

    __shared__ float As[32][132];   // [k][i]
    __shared__ float Bs[32][132];   // [k][j]
    __shared__ float sNi[128], sNj[128];

    int t  = threadIdx.x;
    int tx = t & 15;
    int ty = t >> 4;
    int i0 = bi * 128;
    int j0 = bj * 128;

    if (t < 128) sNi[t] = g_n2[i0 + t];
    else         sNj[t - 128] = g_n2[j0 + t - 128];

    float acc[8][8];
    #pragma unroll
    for (int m = 0; m < 8; ++m)
        #pragma unroll
        for (int n = 0; n < 8; ++n) acc[m][n] = 0.0f;

    int lc  = t & 31;   // k within chunk
    int lr0 = t >> 5;   // row sub-index

    for (int k0 = 0; k0 < D; k0 += 32) {
        #pragma unroll
        for (int l = 0; l < 16; ++l) {
            int r = l * 8 + lr0;
            As[lc][r] = g_y[(size_t)(i0 + r) * D + k0 + lc];
            Bs[lc][r] = g_y[(size_t)(j0 + r) * D + k0 + lc];
        }
        __syncthreads();
        #pragma unroll
        for (int k = 0; k < 32; ++k) {
            float a[8], b[8];
            #pragma unroll
            for (int m = 0; m < 8; ++m) a[m] = As[k][ty * 8 + m];
            #pragma unroll
            for (int n = 0; n < 8; ++n) b[n] = Bs[k][tx * 8 + n];
            #pragma unroll
            for (int m = 0; m < 8; ++m)
                #pragma unroll
                for (int n = 0; n < 8; ++n)
                    acc[m][n] = fmaf(a[m], b[n], acc[m][n]);
        }
        __syncthreads();
    }

    // epilogue: dist, diag fix, 1/dist, row max + col max
    float rmax[8];   // max over n for each local row m
    float cmax[8];   // max over m for each local col n
    #pragma unroll
    for (int m = 0; m < 8; ++m) { rmax[m] = 0.0f; cmax[m] = 0.0f; }

    bool diag_tile = (bi == bj);

    #pragma unroll
    for (int m = 0; m < 8; ++m) {
        int i = i0 + ty * 8 + m;
        float ni = sNi[ty * 8 + m];
        #pragma unroll
        for (int n = 0; n < 8; ++n) {
            int j = j0 + tx * 8 + n;
            float d2 = ni + sNj[tx * 8 + n] - 2.0f * acc[m][n];
            float dist = sqrtf(fmaxf(d2, CLAMP_MIN));
            if (i == j) dist = dist + 10.0f * (1.0f - dist);  // diag -> ~10
            float inv = 1.0f / dist;
            rmax[m] = fmaxf(rmax[m], inv);
            cmax[n] = fmaxf(cmax[n], inv);
        }
    }

    // row reduction across tx (16-lane groups share the same rows)
    #pragma unroll
    for (int m = 0; m < 8; ++m) {
        float v = rmax[m];
        #pragma unroll
        for (int o = 8; o; o >>= 1) v = fmaxf(v, __shfl_xor_sync(0xffffffffu, v, o));
        if (tx == 0)
            atomicMax((int*)&g_rowmax[i0 + ty * 8 + m], __float_as_int(v));
    }

    // column reduction across ty (crosses warps -> via smem), skipped on diag tiles
    if (!diag_tile) {
        __shared__ float sC[16][136];   // padded to de-phase banks per ty-row
        #pragma unroll
        for (int n = 0; n < 8; ++n) sC[ty][tx * 8 + n] = cmax[n];
        __syncthreads();
        if (t < 128) {
            float v = sC[0][t];
            #pragma unroll
            for (int r = 1; r < 16; ++r) v = fmaxf(v, sC[r][t]);
            atomicMax((int*)&g_rowmax[j0 + t], __float_as_int(v));
        }
    }
}

// ---- final mean ----
__global__ void k_final(float* __restrict__ out) {
    int t = threadIdx.x;
    float s = 0.0f;
    for (int i = t; i < N; i += 256) s += g_rowmax[i];
    __shared__ float sm[8];
    #pragma unroll
    for (int o = 16; o; o >>= 1) s += __shfl_xor_sync(0xffffffffu, s, o);
    if ((t & 31) == 0) sm[t >> 5] = s;
    __syncthreads();
    if (t < 8) {
        float a = sm[t];
        #pragma unroll
        for (int o = 4; o; o >>= 1) a += __shfl_xor_sync(0xffu, a, o);
        if (t == 0) out[0] = a * (1.0f / (float)N);
    }
}

extern "C" void kernel_launch(void* const* d_in, const int* in_sizes, int n_in,
                              void* d_out, int out_size) {
    const float* x = (const float*)d_in[0];
    float* out = (float*)d_out;

    k_init<<<32, 256>>>();
    k_normalize<<<N, 256>>>(x);
    k_colsum<<<32, 256>>>();
    k_center<<<N, 256>>>();
    dim3 grid(64, 64);
    k_dist<<<grid, 256>>>();
    k_final<<<1, 256>>>(out);
}

// round 4
// speedup vs baseline: 4.3839x; 2.4877x over previous
#include <cuda_runtime.h>
#include <cuda_bf16.h>
#include <math.h>
#include <stdint.h>

#define N 8192
#define D 256
#define CLAMP_MIN 1e-30f

// ---------------- device scratch (no allocations allowed) ----------------
__device__ float g_y[(size_t)N * D];                 // normalized vectors (fp32)
__device__ float g_colsum[D];
__device__ float g_n2[N];                            // ||z_i||^2 after centering
__device__ float g_rowmax[N];                        // max_j 1/dist (bits monotone)
__device__ __nv_bfloat16 g_hi[(size_t)N * D];        // bf16 hi part of z
__device__ __nv_bfloat16 g_lo[(size_t)N * D];        // bf16 lo part of z

__device__ __forceinline__ uint32_t smem_u32(const void* p) {
    return (uint32_t)__cvta_generic_to_shared(p);
}

// ---------------- sm_80-era building blocks (compile for plain sm_103) ----
__device__ __forceinline__ void ldsm_x4(uint32_t addr, uint32_t* r) {
    asm volatile("ldmatrix.sync.aligned.m8n8.x4.shared.b16 {%0,%1,%2,%3}, [%4];"
                 : "=r"(r[0]), "=r"(r[1]), "=r"(r[2]), "=r"(r[3]) : "r"(addr));
}
__device__ __forceinline__ void mma16816(float* c, const uint32_t* a, const uint32_t* b) {
    asm volatile(
        "mma.sync.aligned.m16n8k16.row.col.f32.bf16.bf16.f32 "
        "{%0,%1,%2,%3}, {%4,%5,%6,%7}, {%8,%9}, {%0,%1,%2,%3};"
        : "+f"(c[0]), "+f"(c[1]), "+f"(c[2]), "+f"(c[3])
        : "r"(a[0]), "r"(a[1]), "r"(a[2]), "r"(a[3]), "r"(b[0]), "r"(b[1]));
}
#define CP_ASYNC16(dst, src) \
    asm volatile("cp.async.cg.shared.global [%0], [%1], 16;" :: "r"(dst), "l"(src))
#define CP_COMMIT() asm volatile("cp.async.commit_group;" ::: "memory")
#define CP_WAIT0()  asm volatile("cp.async.wait_group 0;" ::: "memory")

// ---------------- init: zero accumulators ----------------
__global__ void k_init() {
    int idx = blockIdx.x * 256 + threadIdx.x;
    if (idx < N) g_rowmax[idx] = 0.0f;
    if (idx < D) g_colsum[idx] = 0.0f;
}

// ---------------- row L2-normalize: warp per row ----------------
__global__ __launch_bounds__(256) void k_normalize(const float* __restrict__ x) {
    int w = threadIdx.x >> 5, lane = threadIdx.x & 31;
    int row = blockIdx.x * 8 + w;
    const float4* x4 = (const float4*)(x + (size_t)row * D);
    float4 a = x4[lane * 2], b = x4[lane * 2 + 1];
    float s = a.x * a.x + a.y * a.y + a.z * a.z + a.w * a.w
            + b.x * b.x + b.y * b.y + b.z * b.z + b.w * b.w;
    #pragma unroll
    for (int o = 16; o; o >>= 1) s += __shfl_xor_sync(0xffffffffu, s, o);
    float inv = 1.0f / sqrtf(s);
    float4* y4 = (float4*)(g_y + (size_t)row * D);
    a.x *= inv; a.y *= inv; a.z *= inv; a.w *= inv;
    b.x *= inv; b.y *= inv; b.z *= inv; b.w *= inv;
    y4[lane * 2] = a; y4[lane * 2 + 1] = b;
}

// ---------------- column sums of normalized matrix ----------------
__global__ __launch_bounds__(256) void k_colsum() {
    int t = threadIdx.x;
    int r0 = blockIdx.x * 32;
    float s = 0.0f;
    #pragma unroll 8
    for (int r = 0; r < 32; ++r) s += g_y[(size_t)(r0 + r) * D + t];
    atomicAdd(&g_colsum[t], s);
}

// ---------------- center + n2 + bf16 hi/lo split: warp per row ----------------
__global__ __launch_bounds__(256) void k_prep() {
    int w = threadIdx.x >> 5, lane = threadIdx.x & 31;
    int row = blockIdx.x * 8 + w;
    const float4* y4 = (const float4*)(g_y + (size_t)row * D);
    const float4* c4 = (const float4*)g_colsum;
    float z[8];
    {
        float4 a = y4[lane * 2], b = y4[lane * 2 + 1];
        float4 ca = c4[lane * 2], cb = c4[lane * 2 + 1];
        const float invn = 1.0f / (float)N;
        z[0] = a.x - ca.x * invn; z[1] = a.y - ca.y * invn;
        z[2] = a.z - ca.z * invn; z[3] = a.w - ca.w * invn;
        z[4] = b.x - cb.x * invn; z[5] = b.y - cb.y * invn;
        z[6] = b.z - cb.z * invn; z[7] = b.w - cb.w * invn;
    }
    float s = 0.0f;
    unsigned short hb[8], lb[8];
    #pragma unroll
    for (int e = 0; e < 8; ++e) {
        s += z[e] * z[e];
        __nv_bfloat16 h = __float2bfloat16_rn(z[e]);
        float hf = __bfloat162float(h);
        __nv_bfloat16 l = __float2bfloat16_rn(z[e] - hf);
        hb[e] = *(unsigned short*)&h;
        lb[e] = *(unsigned short*)&l;
    }
    #pragma unroll
    for (int o = 16; o; o >>= 1) s += __shfl_xor_sync(0xffffffffu, s, o);
    if (lane == 0) g_n2[row] = s;
    uint4 hv, lv;
    hv.x = (uint32_t)hb[0] | ((uint32_t)hb[1] << 16);
    hv.y = (uint32_t)hb[2] | ((uint32_t)hb[3] << 16);
    hv.z = (uint32_t)hb[4] | ((uint32_t)hb[5] << 16);
    hv.w = (uint32_t)hb[6] | ((uint32_t)hb[7] << 16);
    lv.x = (uint32_t)lb[0] | ((uint32_t)lb[1] << 16);
    lv.y = (uint32_t)lb[2] | ((uint32_t)lb[3] << 16);
    lv.z = (uint32_t)lb[4] | ((uint32_t)lb[5] << 16);
    lv.w = (uint32_t)lb[6] | ((uint32_t)lb[7] << 16);
    ((uint4*)(g_hi + (size_t)row * D))[lane] = hv;
    ((uint4*)(g_lo + (size_t)row * D))[lane] = lv;
}

// ---------------- fused mma.sync Gram + distance + row/col max ----------------
// 128x128 tile per CTA (upper triangle only), 512 threads = 4x4 warp grid,
// 32x32 warp tile via m16n8k16 bf16 mma, hi/lo split (3 products).
// K chunks of 64, double-buffered with cp.async.
#define ROWB 144                 // padded smem row: 64 bf16 = 128B + 16B pad
#define SLAB (128 * ROWB)        // 18432 B
#define SLABS4 (4 * SLAB)        // Ah, Al, Bh, Bl
#define SMEM_DYN (2 * SLABS4 + 4 * 512 + 1024)

__global__ __launch_bounds__(512) void k_dist() {
    int bi = blockIdx.y, bj = blockIdx.x;
    if (bj < bi) return;

    extern __shared__ uint8_t dyn_smem[];
    uintptr_t base = ((uintptr_t)dyn_smem + 1023) & ~(uintptr_t)1023;
    uint8_t* slab = (uint8_t*)base;                       // 2 buffers x 4 slabs
    float* sNi = (float*)(base + 2 * SLABS4);
    float* sNj = (float*)(base + 2 * SLABS4 + 512);
    float* sRow = (float*)(base + 2 * SLABS4 + 1024);
    float* sCol = (float*)(base + 2 * SLABS4 + 1536);

    int t = threadIdx.x;
    int lid = t & 31, w = t >> 5;
    int warp_m = w & 3, warp_n = w >> 2;
    int m_base = warp_m * 32, n_base = warp_n * 32;
    int i0 = bi * 128, j0 = bj * 128;
    bool diag = (bi == bj);

    if (t < 128) { sNi[t] = g_n2[i0 + t]; sRow[t] = 0.0f; sCol[t] = 0.0f; }
    else if (t < 256) sNj[t - 128] = g_n2[j0 + t - 128];

    const uint8_t* gh = (const uint8_t*)g_hi;
    const uint8_t* gl = (const uint8_t*)g_lo;
    uint32_t slab_s = smem_u32(slab);

    // per-thread copy mapping: 8 x 16B per chunk (2 per slab)
    int crow = t >> 3, cq = t & 7;          // covers rows 0..63 / q 0..7 per 512-thr pass
    // issue cp.async for chunk kb into buffer buf
    auto load_chunk = [&](int kb, int buf) {
        uint32_t dst0 = slab_s + buf * SLABS4;
        #pragma unroll
        for (int s = 0; s < 4; ++s) {
            const uint8_t* src = (s & 1) ? gl : gh;
            int rbase = (s < 2) ? i0 : j0;
            #pragma unroll
            for (int it = 0; it < 2; ++it) {
                int row = crow + it * 64;
                const uint8_t* gp = src + (size_t)(rbase + row) * 512
                                  + (size_t)kb * 128 + (size_t)cq * 16;
                uint32_t doff = dst0 + (uint32_t)(s * SLAB + row * ROWB + cq * 16);
                CP_ASYNC16(doff, gp);
            }
        }
    };

    // ldmatrix lane address offsets (within a slab)
    uint32_t aRow = (uint32_t)((m_base + (lid & 15)) * ROWB + ((lid >> 4) << 4));
    uint32_t bRow = (uint32_t)((n_base + (lid & 7) + ((lid >> 4) << 3)) * ROWB
                               + (((lid >> 3) & 1) << 4));

    float acc[2][4][4];
    #pragma unroll
    for (int mt = 0; mt < 2; ++mt)
        #pragma unroll
        for (int nt = 0; nt < 4; ++nt)
            #pragma unroll
            for (int e = 0; e < 4; ++e) acc[mt][nt][e] = 0.0f;

    load_chunk(0, 0);
    CP_COMMIT();

    for (int kb = 0; kb < 4; ++kb) {
        CP_WAIT0();
        __syncthreads();
        if (kb < 3) { load_chunk(kb + 1, (kb + 1) & 1); CP_COMMIT(); }

        uint32_t b0 = slab_s + (kb & 1) * SLABS4;
        uint32_t sAh = b0, sAl = b0 + SLAB, sBh = b0 + 2 * SLAB, sBl = b0 + 3 * SLAB;

        #pragma unroll
        for (int ks = 0; ks < 4; ++ks) {
            uint32_t kofs = ks * 32;
            uint32_t ah0[4], ah1[4], al0[4], al1[4], bh[2][4], bl[2][4];
            ldsm_x4(sAh + aRow + kofs, ah0);
            ldsm_x4(sAh + aRow + kofs + 16 * ROWB, ah1);
            ldsm_x4(sAl + aRow + kofs, al0);
            ldsm_x4(sAl + aRow + kofs + 16 * ROWB, al1);
            ldsm_x4(sBh + bRow + kofs, bh[0]);
            ldsm_x4(sBh + bRow + kofs + 16 * ROWB, bh[1]);
            ldsm_x4(sBl + bRow + kofs, bl[0]);
            ldsm_x4(sBl + bRow + kofs + 16 * ROWB, bl[1]);
            #pragma unroll
            for (int mt = 0; mt < 2; ++mt) {
                const uint32_t* Ah = mt ? ah1 : ah0;
                const uint32_t* Al = mt ? al1 : al0;
                #pragma unroll
                for (int nh = 0; nh < 2; ++nh)
                    #pragma unroll
                    for (int sb = 0; sb < 2; ++sb) {
                        float* c = acc[mt][nh * 2 + sb];
                        mma16816(c, Ah, &bh[nh][sb * 2]);   // hi*hi
                        mma16816(c, Ah, &bl[nh][sb * 2]);   // hi*lo
                        mma16816(c, Al, &bh[nh][sb * 2]);   // lo*hi
                    }
            }
        }
        __syncthreads();   // all warps done reading this buffer before refill
    }

    // ---------------- epilogue ----------------
    float rmax[2][2];                 // [mt][row-half]
    float cmax[4][2];                 // [nt][col-parity]
    #pragma unroll
    for (int a = 0; a < 2; ++a) { rmax[a][0] = 0.0f; rmax[a][1] = 0.0f; }
    #pragma unroll
    for (int a = 0; a < 4; ++a) { cmax[a][0] = 0.0f; cmax[a][1] = 0.0f; }

    #pragma unroll
    for (int mt = 0; mt < 2; ++mt) {
        int r0 = m_base + mt * 16 + (lid >> 2);
        float ni0 = sNi[r0], ni1 = sNi[r0 + 8];
        int gi0 = i0 + r0;
        #pragma unroll
        for (int nt = 0; nt < 4; ++nt) {
            int c0 = n_base + nt * 8 + (lid & 3) * 2;
            float nj0 = sNj[c0], nj1 = sNj[c0 + 1];
            int gj0 = j0 + c0;
            const float* dd = acc[mt][nt];
            float v00 = rsqrtf(fmaxf(ni0 + nj0 - 2.0f * dd[0], CLAMP_MIN));
            float v01 = rsqrtf(fmaxf(ni0 + nj1 - 2.0f * dd[1], CLAMP_MIN));
            float v10 = rsqrtf(fmaxf(ni1 + nj0 - 2.0f * dd[2], CLAMP_MIN));
            float v11 = rsqrtf(fmaxf(ni1 + nj1 - 2.0f * dd[3], CLAMP_MIN));
            if (gi0 == gj0) v00 = 0.0f;          // diagonal: 1/10 never a row max
            if (gi0 == gj0 + 1) v01 = 0.0f;
            if (gi0 + 8 == gj0) v10 = 0.0f;
            if (gi0 + 8 == gj0 + 1) v11 = 0.0f;
            rmax[mt][0] = fmaxf(rmax[mt][0], fmaxf(v00, v01));
            rmax[mt][1] = fmaxf(rmax[mt][1], fmaxf(v10, v11));
            cmax[nt][0] = fmaxf(cmax[nt][0], fmaxf(v00, v10));
            cmax[nt][1] = fmaxf(cmax[nt][1], fmaxf(v01, v11));
        }
    }

    // row-max: lanes sharing l>>2 hold same rows; reduce across l&3
    #pragma unroll
    for (int mt = 0; mt < 2; ++mt)
        #pragma unroll
        for (int h = 0; h < 2; ++h) {
            float v = rmax[mt][h];
            v = fmaxf(v, __shfl_xor_sync(0xffffffffu, v, 1));
            v = fmaxf(v, __shfl_xor_sync(0xffffffffu, v, 2));
            if ((lid & 3) == 0)
                atomicMax((int*)&sRow[m_base + mt * 16 + h * 8 + (lid >> 2)],
                          __float_as_int(v));
        }
    // col-max: lanes sharing l&3 hold same cols; reduce across l>>2
    if (!diag) {
        #pragma unroll
        for (int nt = 0; nt < 4; ++nt)
            #pragma unroll
            for (int e = 0; e < 2; ++e) {
                float v = cmax[nt][e];
                v = fmaxf(v, __shfl_xor_sync(0xffffffffu, v, 4));
                v = fmaxf(v, __shfl_xor_sync(0xffffffffu, v, 8));
                v = fmaxf(v, __shfl_xor_sync(0xffffffffu, v, 16));
                if (lid < 4)
                    atomicMax((int*)&sCol[n_base + nt * 8 + lid * 2 + e],
                              __float_as_int(v));
            }
    }
    __syncthreads();
    if (t < 128) {
        atomicMax((int*)&g_rowmax[i0 + t], __float_as_int(sRow[t]));
        if (!diag)
            atomicMax((int*)&g_rowmax[j0 + t], __float_as_int(sCol[t]));
    }
}

// ---------------- final mean ----------------
__global__ void k_final(float* __restrict__ out) {
    int t = threadIdx.x;
    float s = 0.0f;
    #pragma unroll 8
    for (int i = t; i < N; i += 256) s += g_rowmax[i];
    __shared__ float sm[8];
    #pragma unroll
    for (int o = 16; o; o >>= 1) s += __shfl_xor_sync(0xffffffffu, s, o);
    if ((t & 31) == 0) sm[t >> 5] = s;
    __syncthreads();
    if (t < 8) {
        float a = sm[t];
        #pragma unroll
        for (int o = 4; o; o >>= 1) a += __shfl_xor_sync(0xffu, a, o);
        if (t == 0) out[0] = a * (1.0f / (float)N);
    }
}

extern "C" void kernel_launch(void* const* d_in, const int* in_sizes, int n_in,
                              void* d_out, int out_size) {
    const float* x = (const float*)d_in[0];
    float* out = (float*)d_out;

    cudaFuncSetAttribute(k_dist, cudaFuncAttributeMaxDynamicSharedMemorySize, SMEM_DYN);

    k_init<<<32, 256>>>();
    k_normalize<<<N / 8, 256>>>(x);
    k_colsum<<<N / 32, 256>>>();
    k_prep<<<N / 8, 256>>>();
    dim3 grid(64, 64);
    k_dist<<<grid, 512, SMEM_DYN>>>();
    k_final<<<1, 256>>>(out);
}

// round 5
// speedup vs baseline: 5.3709x; 1.2251x over previous
#include <cuda_runtime.h>
#include <cuda_bf16.h>
#include <math.h>
#include <stdint.h>

#define N 8192
#define D 256
#define CLAMP_MIN 1e-30f

// ---------------- device scratch (no allocations allowed) ----------------
__device__ float g_y[(size_t)N * D];                 // normalized vectors (fp32)
__device__ float g_colsum[D];
__device__ float g_n2[N];                            // ||z_i||^2 after centering
__device__ float g_rowmax[N];                        // max_j 1/dist (bits monotone)
__device__ __nv_bfloat16 g_hi[(size_t)N * D];        // bf16 hi part of z
__device__ __nv_bfloat16 g_lo[(size_t)N * D];        // bf16 lo part of z

__device__ __forceinline__ uint32_t smem_u32(const void* p) {
    return (uint32_t)__cvta_generic_to_shared(p);
}

// ---------------- sm_80-era building blocks (compile for plain sm_103) ----
__device__ __forceinline__ void ldsm_x4(uint32_t addr, uint32_t* r) {
    asm volatile("ldmatrix.sync.aligned.m8n8.x4.shared.b16 {%0,%1,%2,%3}, [%4];"
                 : "=r"(r[0]), "=r"(r[1]), "=r"(r[2]), "=r"(r[3]) : "r"(addr));
}
__device__ __forceinline__ void mma16816(float* c, const uint32_t* a, const uint32_t* b) {
    asm volatile(
        "mma.sync.aligned.m16n8k16.row.col.f32.bf16.bf16.f32 "
        "{%0,%1,%2,%3}, {%4,%5,%6,%7}, {%8,%9}, {%0,%1,%2,%3};"
        : "+f"(c[0]), "+f"(c[1]), "+f"(c[2]), "+f"(c[3])
        : "r"(a[0]), "r"(a[1]), "r"(a[2]), "r"(a[3]), "r"(b[0]), "r"(b[1]));
}
#define CP_ASYNC16(dst, src) \
    asm volatile("cp.async.cg.shared.global [%0], [%1], 16;" :: "r"(dst), "l"(src))
#define CP_COMMIT() asm volatile("cp.async.commit_group;" ::: "memory")
#define CP_WAIT0()  asm volatile("cp.async.wait_group 0;" ::: "memory")

// ---------------- init: zero accumulators ----------------
__global__ void k_init() {
    int idx = blockIdx.x * 256 + threadIdx.x;
    if (idx < N) g_rowmax[idx] = 0.0f;
    if (idx < D) g_colsum[idx] = 0.0f;
}

// ---------------- row L2-normalize + fused column-sum: warp per row -------
__global__ __launch_bounds__(256) void k_normalize(const float* __restrict__ x) {
    __shared__ float scol[8][256];
    int w = threadIdx.x >> 5, lane = threadIdx.x & 31;
    int row = blockIdx.x * 8 + w;
    const float4* x4 = (const float4*)(x + (size_t)row * D);
    float4 a = x4[lane * 2], b = x4[lane * 2 + 1];
    float s = a.x * a.x + a.y * a.y + a.z * a.z + a.w * a.w
            + b.x * b.x + b.y * b.y + b.z * b.z + b.w * b.w;
    #pragma unroll
    for (int o = 16; o; o >>= 1) s += __shfl_xor_sync(0xffffffffu, s, o);
    float inv = 1.0f / sqrtf(s);
    float4* y4 = (float4*)(g_y + (size_t)row * D);
    a.x *= inv; a.y *= inv; a.z *= inv; a.w *= inv;
    b.x *= inv; b.y *= inv; b.z *= inv; b.w *= inv;
    y4[lane * 2] = a; y4[lane * 2 + 1] = b;
    // stage per-warp (per-row) contribution to column sums
    ((float4*)scol[w])[lane * 2] = a;
    ((float4*)scol[w])[lane * 2 + 1] = b;
    __syncthreads();
    int t = threadIdx.x;          // column index 0..255
    float cs = scol[0][t];
    #pragma unroll
    for (int r = 1; r < 8; ++r) cs += scol[r][t];
    atomicAdd(&g_colsum[t], cs);
}

// ---------------- center + n2 + bf16 hi/lo split: warp per row ----------------
__global__ __launch_bounds__(256) void k_prep() {
    int w = threadIdx.x >> 5, lane = threadIdx.x & 31;
    int row = blockIdx.x * 8 + w;
    const float4* y4 = (const float4*)(g_y + (size_t)row * D);
    const float4* c4 = (const float4*)g_colsum;
    float z[8];
    {
        float4 a = y4[lane * 2], b = y4[lane * 2 + 1];
        float4 ca = c4[lane * 2], cb = c4[lane * 2 + 1];
        const float invn = 1.0f / (float)N;
        z[0] = a.x - ca.x * invn; z[1] = a.y - ca.y * invn;
        z[2] = a.z - ca.z * invn; z[3] = a.w - ca.w * invn;
        z[4] = b.x - cb.x * invn; z[5] = b.y - cb.y * invn;
        z[6] = b.z - cb.z * invn; z[7] = b.w - cb.w * invn;
    }
    float s = 0.0f;
    unsigned short hb[8], lb[8];
    #pragma unroll
    for (int e = 0; e < 8; ++e) {
        s += z[e] * z[e];
        __nv_bfloat16 h = __float2bfloat16_rn(z[e]);
        float hf = __bfloat162float(h);
        __nv_bfloat16 l = __float2bfloat16_rn(z[e] - hf);
        hb[e] = *(unsigned short*)&h;
        lb[e] = *(unsigned short*)&l;
    }
    #pragma unroll
    for (int o = 16; o; o >>= 1) s += __shfl_xor_sync(0xffffffffu, s, o);
    if (lane == 0) g_n2[row] = s;
    uint4 hv, lv;
    hv.x = (uint32_t)hb[0] | ((uint32_t)hb[1] << 16);
    hv.y = (uint32_t)hb[2] | ((uint32_t)hb[3] << 16);
    hv.z = (uint32_t)hb[4] | ((uint32_t)hb[5] << 16);
    hv.w = (uint32_t)hb[6] | ((uint32_t)hb[7] << 16);
    lv.x = (uint32_t)lb[0] | ((uint32_t)lb[1] << 16);
    lv.y = (uint32_t)lb[2] | ((uint32_t)lb[3] << 16);
    lv.z = (uint32_t)lb[4] | ((uint32_t)lb[5] << 16);
    lv.w = (uint32_t)lb[6] | ((uint32_t)lb[7] << 16);
    ((uint4*)(g_hi + (size_t)row * D))[lane] = hv;
    ((uint4*)(g_lo + (size_t)row * D))[lane] = lv;
}

// ---------------- fused mma.sync Gram + distance + row/col max ----------------
// 128x128 tile per CTA (upper triangle only), 512 threads = 4x4 warp grid.
// 2-product split: dot ~= hi_a*hi_b + lo_a*hi_b  (B-lo slab eliminated).
// K chunks of 64, double-buffered with cp.async.
#define ROWB 144                 // padded smem row: 64 bf16 = 128B + 16B pad
#define SLAB (128 * ROWB)        // 18432 B
#define SLABS3 (3 * SLAB)        // Ah, Al, Bh
#define SMEM_DYN (2 * SLABS3 + 4 * 512 + 1024)

__global__ __launch_bounds__(512) void k_dist() {
    int bi = blockIdx.y, bj = blockIdx.x;
    if (bj < bi) return;

    extern __shared__ uint8_t dyn_smem[];
    uintptr_t base = ((uintptr_t)dyn_smem + 1023) & ~(uintptr_t)1023;
    uint8_t* slab = (uint8_t*)base;                       // 2 buffers x 3 slabs
    float* sNi = (float*)(base + 2 * SLABS3);
    float* sNj = (float*)(base + 2 * SLABS3 + 512);
    float* sRow = (float*)(base + 2 * SLABS3 + 1024);
    float* sCol = (float*)(base + 2 * SLABS3 + 1536);

    int t = threadIdx.x;
    int lid = t & 31, w = t >> 5;
    int warp_m = w & 3, warp_n = w >> 2;
    int m_base = warp_m * 32, n_base = warp_n * 32;
    int i0 = bi * 128, j0 = bj * 128;
    bool diag = (bi == bj);

    if (t < 128) { sNi[t] = g_n2[i0 + t]; sRow[t] = 0.0f; sCol[t] = 0.0f; }
    else if (t < 256) sNj[t - 128] = g_n2[j0 + t - 128];

    const uint8_t* gh = (const uint8_t*)g_hi;
    const uint8_t* gl = (const uint8_t*)g_lo;
    uint32_t slab_s = smem_u32(slab);

    // per-thread copy mapping: 6 x 16B per chunk (2 per slab)
    int crow = t >> 3, cq = t & 7;
    auto load_chunk = [&](int kb, int buf) {
        uint32_t dst0 = slab_s + buf * SLABS3;
        #pragma unroll
        for (int s = 0; s < 3; ++s) {
            const uint8_t* src = (s == 1) ? gl : gh;     // Ah, Al, Bh
            int rbase = (s < 2) ? i0 : j0;
            #pragma unroll
            for (int it = 0; it < 2; ++it) {
                int row = crow + it * 64;
                const uint8_t* gp = src + (size_t)(rbase + row) * 512
                                  + (size_t)kb * 128 + (size_t)cq * 16;
                uint32_t doff = dst0 + (uint32_t)(s * SLAB + row * ROWB + cq * 16);
                CP_ASYNC16(doff, gp);
            }
        }
    };

    // ldmatrix lane address offsets (within a slab)
    uint32_t aRow = (uint32_t)((m_base + (lid & 15)) * ROWB + ((lid >> 4) << 4));
    uint32_t bRow = (uint32_t)((n_base + (lid & 7) + ((lid >> 4) << 3)) * ROWB
                               + (((lid >> 3) & 1) << 4));

    float acc[2][4][4];
    #pragma unroll
    for (int mt = 0; mt < 2; ++mt)
        #pragma unroll
        for (int nt = 0; nt < 4; ++nt)
            #pragma unroll
            for (int e = 0; e < 4; ++e) acc[mt][nt][e] = 0.0f;

    load_chunk(0, 0);
    CP_COMMIT();

    for (int kb = 0; kb < 4; ++kb) {
        CP_WAIT0();
        __syncthreads();
        if (kb < 3) { load_chunk(kb + 1, (kb + 1) & 1); CP_COMMIT(); }

        uint32_t b0 = slab_s + (kb & 1) * SLABS3;
        uint32_t sAh = b0, sAl = b0 + SLAB, sBh = b0 + 2 * SLAB;

        #pragma unroll
        for (int ks = 0; ks < 4; ++ks) {
            uint32_t kofs = ks * 32;
            uint32_t ah0[4], ah1[4], al0[4], al1[4], bh[2][4];
            ldsm_x4(sAh + aRow + kofs, ah0);
            ldsm_x4(sAh + aRow + kofs + 16 * ROWB, ah1);
            ldsm_x4(sAl + aRow + kofs, al0);
            ldsm_x4(sAl + aRow + kofs + 16 * ROWB, al1);
            ldsm_x4(sBh + bRow + kofs, bh[0]);
            ldsm_x4(sBh + bRow + kofs + 16 * ROWB, bh[1]);
            #pragma unroll
            for (int mt = 0; mt < 2; ++mt) {
                const uint32_t* Ah = mt ? ah1 : ah0;
                const uint32_t* Al = mt ? al1 : al0;
                #pragma unroll
                for (int nh = 0; nh < 2; ++nh)
                    #pragma unroll
                    for (int sb = 0; sb < 2; ++sb) {
                        float* c = acc[mt][nh * 2 + sb];
                        mma16816(c, Ah, &bh[nh][sb * 2]);   // hi*hi
                        mma16816(c, Al, &bh[nh][sb * 2]);   // lo*hi
                    }
            }
        }
        __syncthreads();   // all warps done reading this buffer before refill
    }

    // ---------------- epilogue ----------------
    float rmax[2][2];                 // [mt][row-half]
    float cmax[4][2];                 // [nt][col-parity]
    #pragma unroll
    for (int a = 0; a < 2; ++a) { rmax[a][0] = 0.0f; rmax[a][1] = 0.0f; }
    #pragma unroll
    for (int a = 0; a < 4; ++a) { cmax[a][0] = 0.0f; cmax[a][1] = 0.0f; }

    #pragma unroll
    for (int mt = 0; mt < 2; ++mt) {
        int r0 = m_base + mt * 16 + (lid >> 2);
        float ni0 = sNi[r0], ni1 = sNi[r0 + 8];
        int gi0 = i0 + r0;
        #pragma unroll
        for (int nt = 0; nt < 4; ++nt) {
            int c0 = n_base + nt * 8 + (lid & 3) * 2;
            float nj0 = sNj[c0], nj1 = sNj[c0 + 1];
            int gj0 = j0 + c0;
            const float* dd = acc[mt][nt];
            float v00 = rsqrtf(fmaxf(ni0 + nj0 - 2.0f * dd[0], CLAMP_MIN));
            float v01 = rsqrtf(fmaxf(ni0 + nj1 - 2.0f * dd[1], CLAMP_MIN));
            float v10 = rsqrtf(fmaxf(ni1 + nj0 - 2.0f * dd[2], CLAMP_MIN));
            float v11 = rsqrtf(fmaxf(ni1 + nj1 - 2.0f * dd[3], CLAMP_MIN));
            if (gi0 == gj0) v00 = 0.0f;          // diagonal: 1/10 never a row max
            if (gi0 == gj0 + 1) v01 = 0.0f;
            if (gi0 + 8 == gj0) v10 = 0.0f;
            if (gi0 + 8 == gj0 + 1) v11 = 0.0f;
            rmax[mt][0] = fmaxf(rmax[mt][0], fmaxf(v00, v01));
            rmax[mt][1] = fmaxf(rmax[mt][1], fmaxf(v10, v11));
            cmax[nt][0] = fmaxf(cmax[nt][0], fmaxf(v00, v10));
            cmax[nt][1] = fmaxf(cmax[nt][1], fmaxf(v01, v11));
        }
    }

    // row-max: lanes sharing l>>2 hold same rows; reduce across l&3
    #pragma unroll
    for (int mt = 0; mt < 2; ++mt)
        #pragma unroll
        for (int h = 0; h < 2; ++h) {
            float v = rmax[mt][h];
            v = fmaxf(v, __shfl_xor_sync(0xffffffffu, v, 1));
            v = fmaxf(v, __shfl_xor_sync(0xffffffffu, v, 2));
            if ((lid & 3) == 0)
                atomicMax((int*)&sRow[m_base + mt * 16 + h * 8 + (lid >> 2)],
                          __float_as_int(v));
        }
    // col-max: lanes sharing l&3 hold same cols; reduce across l>>2
    if (!diag) {
        #pragma unroll
        for (int nt = 0; nt < 4; ++nt)
            #pragma unroll
            for (int e = 0; e < 2; ++e) {
                float v = cmax[nt][e];
                v = fmaxf(v, __shfl_xor_sync(0xffffffffu, v, 4));
                v = fmaxf(v, __shfl_xor_sync(0xffffffffu, v, 8));
                v = fmaxf(v, __shfl_xor_sync(0xffffffffu, v, 16));
                if (lid < 4)
                    atomicMax((int*)&sCol[n_base + nt * 8 + lid * 2 + e],
                              __float_as_int(v));
            }
    }
    __syncthreads();
    if (t < 128) {
        atomicMax((int*)&g_rowmax[i0 + t], __float_as_int(sRow[t]));
        if (!diag)
            atomicMax((int*)&g_rowmax[j0 + t], __float_as_int(sCol[t]));
    }
}

// ---------------- final mean ----------------
__global__ void k_final(float* __restrict__ out) {
    int t = threadIdx.x;
    float s = 0.0f;
    #pragma unroll 8
    for (int i = t; i < N; i += 256) s += g_rowmax[i];
    __shared__ float sm[8];
    #pragma unroll
    for (int o = 16; o; o >>= 1) s += __shfl_xor_sync(0xffffffffu, s, o);
    if ((t & 31) == 0) sm[t >> 5] = s;
    __syncthreads();
    if (t < 8) {
        float a = sm[t];
        #pragma unroll
        for (int o = 4; o; o >>= 1) a += __shfl_xor_sync(0xffu, a, o);
        if (t == 0) out[0] = a * (1.0f / (float)N);
    }
}

extern "C" void kernel_launch(void* const* d_in, const int* in_sizes, int n_in,
                              void* d_out, int out_size) {
    const float* x = (const float*)d_in[0];
    float* out = (float*)d_out;

    cudaFuncSetAttribute(k_dist, cudaFuncAttributeMaxDynamicSharedMemorySize, SMEM_DYN);

    k_init<<<32, 256>>>();
    k_normalize<<<N / 8, 256>>>(x);
    k_prep<<<N / 8, 256>>>();
    dim3 grid(64, 64);
    k_dist<<<grid, 512, SMEM_DYN>>>();
    k_final<<<1, 256>>>(out);
}

// round 6
// speedup vs baseline: 7.3432x; 1.3672x over previous
#include <cuda_runtime.h>
#include <cuda_bf16.h>
#include <math.h>
#include <stdint.h>

#define N 8192
#define D 256
#define CLAMP_MIN 1e-30f

// ---------------- device scratch (no allocations allowed) ----------------
__device__ float g_y[(size_t)N * D];                 // normalized vectors (fp32)
__device__ float g_colsum[D];
__device__ float g_n2[N];                            // ||z_i||^2 after centering
__device__ float g_rowmax[N];                        // max_j 1/dist (bits monotone)
__device__ __nv_bfloat16 g_hi[(size_t)N * D];        // bf16 hi part of z
__device__ __nv_bfloat16 g_lo[(size_t)N * D];        // bf16 lo part of z

__device__ __forceinline__ uint32_t smem_u32(const void* p) {
    return (uint32_t)__cvta_generic_to_shared(p);
}
__device__ __forceinline__ uint32_t sw128(uint32_t off) {
    return off ^ ((off >> 3) & 0x70);
}

// ---------------- sm_80-era building blocks (compile for plain sm_103) ----
__device__ __forceinline__ void ldsm_x4(uint32_t addr, uint32_t* r) {
    asm volatile("ldmatrix.sync.aligned.m8n8.x4.shared.b16 {%0,%1,%2,%3}, [%4];"
                 : "=r"(r[0]), "=r"(r[1]), "=r"(r[2]), "=r"(r[3]) : "r"(addr));
}
__device__ __forceinline__ void mma16816(float* c, const uint32_t* a, const uint32_t* b) {
    asm volatile(
        "mma.sync.aligned.m16n8k16.row.col.f32.bf16.bf16.f32 "
        "{%0,%1,%2,%3}, {%4,%5,%6,%7}, {%8,%9}, {%0,%1,%2,%3};"
        : "+f"(c[0]), "+f"(c[1]), "+f"(c[2]), "+f"(c[3])
        : "r"(a[0]), "r"(a[1]), "r"(a[2]), "r"(a[3]), "r"(b[0]), "r"(b[1]));
}
#define CP_ASYNC16(dst, src) \
    asm volatile("cp.async.cg.shared.global [%0], [%1], 16;" :: "r"(dst), "l"(src))
#define CP_COMMIT() asm volatile("cp.async.commit_group;" ::: "memory")
#define CP_WAIT0()  asm volatile("cp.async.wait_group 0;" ::: "memory")

// ---------------- init: zero accumulators ----------------
__global__ void k_init() {
    int idx = blockIdx.x * 256 + threadIdx.x;
    if (idx < N) g_rowmax[idx] = 0.0f;
    if (idx < D) g_colsum[idx] = 0.0f;
}

// ---------------- row L2-normalize + fused column-sum: warp per row -------
__global__ __launch_bounds__(256) void k_normalize(const float* __restrict__ x) {
    __shared__ float scol[8][256];
    int w = threadIdx.x >> 5, lane = threadIdx.x & 31;
    int row = blockIdx.x * 8 + w;
    const float4* x4 = (const float4*)(x + (size_t)row * D);
    float4 a = x4[lane * 2], b = x4[lane * 2 + 1];
    float s = a.x * a.x + a.y * a.y + a.z * a.z + a.w * a.w
            + b.x * b.x + b.y * b.y + b.z * b.z + b.w * b.w;
    #pragma unroll
    for (int o = 16; o; o >>= 1) s += __shfl_xor_sync(0xffffffffu, s, o);
    float inv = 1.0f / sqrtf(s);
    float4* y4 = (float4*)(g_y + (size_t)row * D);
    a.x *= inv; a.y *= inv; a.z *= inv; a.w *= inv;
    b.x *= inv; b.y *= inv; b.z *= inv; b.w *= inv;
    y4[lane * 2] = a; y4[lane * 2 + 1] = b;
    ((float4*)scol[w])[lane * 2] = a;
    ((float4*)scol[w])[lane * 2 + 1] = b;
    __syncthreads();
    int t = threadIdx.x;
    float cs = scol[0][t];
    #pragma unroll
    for (int r = 1; r < 8; ++r) cs += scol[r][t];
    atomicAdd(&g_colsum[t], cs);
}

// ---------------- center + n2 + bf16 hi/lo split: warp per row ----------------
__global__ __launch_bounds__(256) void k_prep() {
    int w = threadIdx.x >> 5, lane = threadIdx.x & 31;
    int row = blockIdx.x * 8 + w;
    const float4* y4 = (const float4*)(g_y + (size_t)row * D);
    const float4* c4 = (const float4*)g_colsum;
    float z[8];
    {
        float4 a = y4[lane * 2], b = y4[lane * 2 + 1];
        float4 ca = c4[lane * 2], cb = c4[lane * 2 + 1];
        const float invn = 1.0f / (float)N;
        z[0] = a.x - ca.x * invn; z[1] = a.y - ca.y * invn;
        z[2] = a.z - ca.z * invn; z[3] = a.w - ca.w * invn;
        z[4] = b.x - cb.x * invn; z[5] = b.y - cb.y * invn;
        z[6] = b.z - cb.z * invn; z[7] = b.w - cb.w * invn;
    }
    float s = 0.0f;
    unsigned short hb[8], lb[8];
    #pragma unroll
    for (int e = 0; e < 8; ++e) {
        s += z[e] * z[e];
        __nv_bfloat16 h = __float2bfloat16_rn(z[e]);
        float hf = __bfloat162float(h);
        __nv_bfloat16 l = __float2bfloat16_rn(z[e] - hf);
        hb[e] = *(unsigned short*)&h;
        lb[e] = *(unsigned short*)&l;
    }
    #pragma unroll
    for (int o = 16; o; o >>= 1) s += __shfl_xor_sync(0xffffffffu, s, o);
    if (lane == 0) g_n2[row] = s;
    uint4 hv, lv;
    hv.x = (uint32_t)hb[0] | ((uint32_t)hb[1] << 16);
    hv.y = (uint32_t)hb[2] | ((uint32_t)hb[3] << 16);
    hv.z = (uint32_t)hb[4] | ((uint32_t)hb[5] << 16);
    hv.w = (uint32_t)hb[6] | ((uint32_t)hb[7] << 16);
    lv.x = (uint32_t)lb[0] | ((uint32_t)lb[1] << 16);
    lv.y = (uint32_t)lb[2] | ((uint32_t)lb[3] << 16);
    lv.z = (uint32_t)lb[4] | ((uint32_t)lb[5] << 16);
    lv.w = (uint32_t)lb[6] | ((uint32_t)lb[7] << 16);
    ((uint4*)(g_hi + (size_t)row * D))[lane] = hv;
    ((uint4*)(g_lo + (size_t)row * D))[lane] = lv;
}

// ---------------- fused mma.sync Gram + distance + row/col max ----------------
// 128x128 tile per CTA (upper triangle only), 512 threads = 4x4 warp grid.
// 2-product split: dot ~= hi_a*hi_b + lo_a*hi_b.
// 128B smem rows with SW128 XOR swizzle (no padding) -> 2 CTAs/SM.
#define SLAB (128 * 128)         // 16384 B per slab
#define SLABS3 (3 * SLAB)        // Ah, Al, Bh
#define SMEM_DYN (2 * SLABS3 + 4 * 512 + 1024)

__global__ __launch_bounds__(512, 2) void k_dist() {
    int bi = blockIdx.y, bj = blockIdx.x;
    if (bj < bi) return;

    extern __shared__ uint8_t dyn_smem[];
    uintptr_t base = ((uintptr_t)dyn_smem + 1023) & ~(uintptr_t)1023;
    uint8_t* slab = (uint8_t*)base;                       // 2 buffers x 3 slabs
    float* sNi = (float*)(base + 2 * SLABS3);
    float* sNj = (float*)(base + 2 * SLABS3 + 512);
    float* sRow = (float*)(base + 2 * SLABS3 + 1024);
    float* sCol = (float*)(base + 2 * SLABS3 + 1536);

    int t = threadIdx.x;
    int lid = t & 31, w = t >> 5;
    int warp_m = w & 3, warp_n = w >> 2;
    int m_base = warp_m * 32, n_base = warp_n * 32;
    int i0 = bi * 128, j0 = bj * 128;
    bool diag = (bi == bj);

    if (t < 128) { sNi[t] = g_n2[i0 + t]; sRow[t] = 0.0f; sCol[t] = 0.0f; }
    else if (t < 256) sNj[t - 128] = g_n2[j0 + t - 128];

    const uint8_t* gh = (const uint8_t*)g_hi;
    const uint8_t* gl = (const uint8_t*)g_lo;
    uint32_t slab_s = smem_u32(slab);

    // per-thread copy mapping: 6 x 16B per chunk (2 per slab), swizzled dst
    int crow = t >> 3, cq = t & 7;
    uint32_t sw_lo = sw128((uint32_t)(crow * 128 + cq * 16));  // same for row, row+64 (bit13 untouched... recompute below)
    auto load_chunk = [&](int kb, int buf) {
        uint32_t dst0 = slab_s + buf * SLABS3;
        #pragma unroll
        for (int s = 0; s < 3; ++s) {
            const uint8_t* src = (s == 1) ? gl : gh;     // Ah, Al, Bh
            int rbase = (s < 2) ? i0 : j0;
            #pragma unroll
            for (int it = 0; it < 2; ++it) {
                int row = crow + it * 64;
                const uint8_t* gp = src + (size_t)(rbase + row) * 512
                                  + (size_t)kb * 128 + (size_t)cq * 16;
                // +64 rows = +8192 B: swizzle bits unaffected (XOR uses bits 4..9)
                uint32_t doff = dst0 + (uint32_t)(s * SLAB + it * 64 * 128) + sw_lo;
                CP_ASYNC16(doff, gp);
            }
        }
    };

    // logical (pre-swizzle) ldmatrix lane offsets within a slab
    uint32_t aOff = (uint32_t)((m_base + (lid & 15)) * 128 + ((lid >> 4) << 4));
    uint32_t bOff = (uint32_t)((n_base + (lid & 7) + ((lid >> 4) << 3)) * 128
                               + (((lid >> 3) & 1) << 4));

    float acc[2][4][4];
    #pragma unroll
    for (int mt = 0; mt < 2; ++mt)
        #pragma unroll
        for (int nt = 0; nt < 4; ++nt)
            #pragma unroll
            for (int e = 0; e < 4; ++e) acc[mt][nt][e] = 0.0f;

    load_chunk(0, 0);
    CP_COMMIT();

    for (int kb = 0; kb < 4; ++kb) {
        CP_WAIT0();
        __syncthreads();
        if (kb < 3) { load_chunk(kb + 1, (kb + 1) & 1); CP_COMMIT(); }

        uint32_t b0 = slab_s + (kb & 1) * SLABS3;
        uint32_t sAh = b0, sAl = b0 + SLAB, sBh = b0 + 2 * SLAB;

        #pragma unroll
        for (int ks = 0; ks < 4; ++ks) {
            uint32_t kofs = ks * 32;
            // swizzled addresses (+16 rows = +2048 B leaves XOR field unchanged)
            uint32_t aS = sw128(aOff + kofs);
            uint32_t bS = sw128(bOff + kofs);
            uint32_t ah0[4], ah1[4], al0[4], al1[4], bh[2][4];
            ldsm_x4(sAh + aS, ah0);
            ldsm_x4(sAh + aS + 16 * 128, ah1);
            ldsm_x4(sAl + aS, al0);
            ldsm_x4(sAl + aS + 16 * 128, al1);
            ldsm_x4(sBh + bS, bh[0]);
            ldsm_x4(sBh + bS + 16 * 128, bh[1]);
            #pragma unroll
            for (int mt = 0; mt < 2; ++mt) {
                const uint32_t* Ah = mt ? ah1 : ah0;
                const uint32_t* Al = mt ? al1 : al0;
                #pragma unroll
                for (int nh = 0; nh < 2; ++nh)
                    #pragma unroll
                    for (int sb = 0; sb < 2; ++sb) {
                        float* c = acc[mt][nh * 2 + sb];
                        mma16816(c, Ah, &bh[nh][sb * 2]);   // hi*hi
                        mma16816(c, Al, &bh[nh][sb * 2]);   // lo*hi
                    }
            }
        }
        __syncthreads();
    }

    // ---------------- epilogue ----------------
    float rmax[2][2];
    float cmax[4][2];
    #pragma unroll
    for (int a = 0; a < 2; ++a) { rmax[a][0] = 0.0f; rmax[a][1] = 0.0f; }
    #pragma unroll
    for (int a = 0; a < 4; ++a) { cmax[a][0] = 0.0f; cmax[a][1] = 0.0f; }

    #pragma unroll
    for (int mt = 0; mt < 2; ++mt) {
        int r0 = m_base + mt * 16 + (lid >> 2);
        float ni0 = sNi[r0], ni1 = sNi[r0 + 8];
        int gi0 = i0 + r0;
        #pragma unroll
        for (int nt = 0; nt < 4; ++nt) {
            int c0 = n_base + nt * 8 + (lid & 3) * 2;
            float nj0 = sNj[c0], nj1 = sNj[c0 + 1];
            int gj0 = j0 + c0;
            const float* dd = acc[mt][nt];
            float v00 = rsqrtf(fmaxf(ni0 + nj0 - 2.0f * dd[0], CLAMP_MIN));
            float v01 = rsqrtf(fmaxf(ni0 + nj1 - 2.0f * dd[1], CLAMP_MIN));
            float v10 = rsqrtf(fmaxf(ni1 + nj0 - 2.0f * dd[2], CLAMP_MIN));
            float v11 = rsqrtf(fmaxf(ni1 + nj1 - 2.0f * dd[3], CLAMP_MIN));
            if (gi0 == gj0) v00 = 0.0f;
            if (gi0 == gj0 + 1) v01 = 0.0f;
            if (gi0 + 8 == gj0) v10 = 0.0f;
            if (gi0 + 8 == gj0 + 1) v11 = 0.0f;
            rmax[mt][0] = fmaxf(rmax[mt][0], fmaxf(v00, v01));
            rmax[mt][1] = fmaxf(rmax[mt][1], fmaxf(v10, v11));
            cmax[nt][0] = fmaxf(cmax[nt][0], fmaxf(v00, v10));
            cmax[nt][1] = fmaxf(cmax[nt][1], fmaxf(v01, v11));
        }
    }

    #pragma unroll
    for (int mt = 0; mt < 2; ++mt)
        #pragma unroll
        for (int h = 0; h < 2; ++h) {
            float v = rmax[mt][h];
            v = fmaxf(v, __shfl_xor_sync(0xffffffffu, v, 1));
            v = fmaxf(v, __shfl_xor_sync(0xffffffffu, v, 2));
            if ((lid & 3) == 0)
                atomicMax((int*)&sRow[m_base + mt * 16 + h * 8 + (lid >> 2)],
                          __float_as_int(v));
        }
    if (!diag) {
        #pragma unroll
        for (int nt = 0; nt < 4; ++nt)
            #pragma unroll
            for (int e = 0; e < 2; ++e) {
                float v = cmax[nt][e];
                v = fmaxf(v, __shfl_xor_sync(0xffffffffu, v, 4));
                v = fmaxf(v, __shfl_xor_sync(0xffffffffu, v, 8));
                v = fmaxf(v, __shfl_xor_sync(0xffffffffu, v, 16));
                if (lid < 4)
                    atomicMax((int*)&sCol[n_base + nt * 8 + lid * 2 + e],
                              __float_as_int(v));
            }
    }
    __syncthreads();
    if (t < 128) {
        atomicMax((int*)&g_rowmax[i0 + t], __float_as_int(sRow[t]));
        if (!diag)
            atomicMax((int*)&g_rowmax[j0 + t], __float_as_int(sCol[t]));
    }
}

// ---------------- final mean ----------------
__global__ void k_final(float* __restrict__ out) {
    int t = threadIdx.x;
    float s = 0.0f;
    #pragma unroll 8
    for (int i = t; i < N; i += 256) s += g_rowmax[i];
    __shared__ float sm[8];
    #pragma unroll
    for (int o = 16; o; o >>= 1) s += __shfl_xor_sync(0xffffffffu, s, o);
    if ((t & 31) == 0) sm[t >> 5] = s;
    __syncthreads();
    if (t < 8) {
        float a = sm[t];
        #pragma unroll
        for (int o = 4; o; o >>= 1) a += __shfl_xor_sync(0xffu, a, o);
        if (t == 0) out[0] = a * (1.0f / (float)N);
    }
}

extern "C" void kernel_launch(void* const* d_in, const int* in_sizes, int n_in,
                              void* d_out, int out_size) {
    const float* x = (const float*)d_in[0];
    float* out = (float*)d_out;

    cudaFuncSetAttribute(k_dist, cudaFuncAttributeMaxDynamicSharedMemorySize, SMEM_DYN);

    k_init<<<32, 256>>>();
    k_normalize<<<N / 8, 256>>>(x);
    k_prep<<<N / 8, 256>>>();
    dim3 grid(64, 64);
    k_dist<<<grid, 512, SMEM_DYN>>>();
    k_final<<<1, 256>>>(out);
}

// round 7
// speedup vs baseline: 7.4067x; 1.0086x over previous
#include <cuda_runtime.h>
#include <cuda_bf16.h>
#include <math.h>
#include <stdint.h>

#define N 8192
#define D 256
#define CLAMP_MIN 1e-30f

// ---------------- device scratch (no allocations allowed) ----------------
__device__ float g_y[(size_t)N * D];                 // normalized vectors (fp32)
__device__ float g_colsum[D];
__device__ float g_n2[N];                            // ||z_i||^2 after centering
__device__ float g_rowmax[N];                        // max_j 1/dist (bits monotone)
__device__ __nv_bfloat16 g_hi[(size_t)N * D];        // bf16 hi part of z
__device__ __nv_bfloat16 g_lo[(size_t)N * D];        // bf16 lo part of z

__device__ __forceinline__ uint32_t smem_u32(const void* p) {
    return (uint32_t)__cvta_generic_to_shared(p);
}
__device__ __forceinline__ uint32_t sw128(uint32_t off) {
    return off ^ ((off >> 3) & 0x70);
}

// ---------------- sm_80-era building blocks (compile for plain sm_103) ----
__device__ __forceinline__ void ldsm_x4(uint32_t addr, uint32_t* r) {
    asm volatile("ldmatrix.sync.aligned.m8n8.x4.shared.b16 {%0,%1,%2,%3}, [%4];"
                 : "=r"(r[0]), "=r"(r[1]), "=r"(r[2]), "=r"(r[3]) : "r"(addr));
}
__device__ __forceinline__ void mma16816(float* c, const uint32_t* a, const uint32_t* b) {
    asm volatile(
        "mma.sync.aligned.m16n8k16.row.col.f32.bf16.bf16.f32 "
        "{%0,%1,%2,%3}, {%4,%5,%6,%7}, {%8,%9}, {%0,%1,%2,%3};"
        : "+f"(c[0]), "+f"(c[1]), "+f"(c[2]), "+f"(c[3])
        : "r"(a[0]), "r"(a[1]), "r"(a[2]), "r"(a[3]), "r"(b[0]), "r"(b[1]));
}
#define CP_ASYNC16(dst, src) \
    asm volatile("cp.async.cg.shared.global [%0], [%1], 16;" :: "r"(dst), "l"(src))
#define CP_COMMIT() asm volatile("cp.async.commit_group;" ::: "memory")
#define CP_WAIT0()  asm volatile("cp.async.wait_group 0;" ::: "memory")

// ---------------- init: zero accumulators ----------------
__global__ void k_init() {
    int idx = blockIdx.x * 256 + threadIdx.x;
    if (idx < N) g_rowmax[idx] = 0.0f;
    if (idx < D) g_colsum[idx] = 0.0f;
}

// ---------------- row L2-normalize + fused column-sum: warp per row -------
__global__ __launch_bounds__(256) void k_normalize(const float* __restrict__ x) {
    __shared__ float scol[8][256];
    int w = threadIdx.x >> 5, lane = threadIdx.x & 31;
    int row = blockIdx.x * 8 + w;
    const float4* x4 = (const float4*)(x + (size_t)row * D);
    float4 a = x4[lane * 2], b = x4[lane * 2 + 1];
    float s = a.x * a.x + a.y * a.y + a.z * a.z + a.w * a.w
            + b.x * b.x + b.y * b.y + b.z * b.z + b.w * b.w;
    #pragma unroll
    for (int o = 16; o; o >>= 1) s += __shfl_xor_sync(0xffffffffu, s, o);
    float inv = 1.0f / sqrtf(s);
    float4* y4 = (float4*)(g_y + (size_t)row * D);
    a.x *= inv; a.y *= inv; a.z *= inv; a.w *= inv;
    b.x *= inv; b.y *= inv; b.z *= inv; b.w *= inv;
    y4[lane * 2] = a; y4[lane * 2 + 1] = b;
    ((float4*)scol[w])[lane * 2] = a;
    ((float4*)scol[w])[lane * 2 + 1] = b;
    __syncthreads();
    int t = threadIdx.x;
    float cs = scol[0][t];
    #pragma unroll
    for (int r = 1; r < 8; ++r) cs += scol[r][t];
    atomicAdd(&g_colsum[t], cs);
}

// ---------------- center + n2 + bf16 hi/lo split: warp per row ----------------
__global__ __launch_bounds__(256) void k_prep() {
    int w = threadIdx.x >> 5, lane = threadIdx.x & 31;
    int row = blockIdx.x * 8 + w;
    const float4* y4 = (const float4*)(g_y + (size_t)row * D);
    const float4* c4 = (const float4*)g_colsum;
    float z[8];
    {
        float4 a = y4[lane * 2], b = y4[lane * 2 + 1];
        float4 ca = c4[lane * 2], cb = c4[lane * 2 + 1];
        const float invn = 1.0f / (float)N;
        z[0] = a.x - ca.x * invn; z[1] = a.y - ca.y * invn;
        z[2] = a.z - ca.z * invn; z[3] = a.w - ca.w * invn;
        z[4] = b.x - cb.x * invn; z[5] = b.y - cb.y * invn;
        z[6] = b.z - cb.z * invn; z[7] = b.w - cb.w * invn;
    }
    float s = 0.0f;
    unsigned short hb[8], lb[8];
    #pragma unroll
    for (int e = 0; e < 8; ++e) {
        s += z[e] * z[e];
        __nv_bfloat16 h = __float2bfloat16_rn(z[e]);
        float hf = __bfloat162float(h);
        __nv_bfloat16 l = __float2bfloat16_rn(z[e] - hf);
        hb[e] = *(unsigned short*)&h;
        lb[e] = *(unsigned short*)&l;
    }
    #pragma unroll
    for (int o = 16; o; o >>= 1) s += __shfl_xor_sync(0xffffffffu, s, o);
    if (lane == 0) g_n2[row] = s;
    uint4 hv, lv;
    hv.x = (uint32_t)hb[0] | ((uint32_t)hb[1] << 16);
    hv.y = (uint32_t)hb[2] | ((uint32_t)hb[3] << 16);
    hv.z = (uint32_t)hb[4] | ((uint32_t)hb[5] << 16);
    hv.w = (uint32_t)hb[6] | ((uint32_t)hb[7] << 16);
    lv.x = (uint32_t)lb[0] | ((uint32_t)lb[1] << 16);
    lv.y = (uint32_t)lb[2] | ((uint32_t)lb[3] << 16);
    lv.z = (uint32_t)lb[4] | ((uint32_t)lb[5] << 16);
    lv.w = (uint32_t)lb[6] | ((uint32_t)lb[7] << 16);
    ((uint4*)(g_hi + (size_t)row * D))[lane] = hv;
    ((uint4*)(g_lo + (size_t)row * D))[lane] = lv;
}

// ---------------- fused mma.sync Gram + distance + row/col max ----------------
// 128x128 tile per CTA (upper triangle only), 512 threads = 4x4 warp grid.
// 2-product split: dot ~= hi_a*hi_b + lo_a*hi_b.
// 128B smem rows with SW128 XOR swizzle (no padding) -> 2 CTAs/SM.
#define SLAB (128 * 128)         // 16384 B per slab
#define SLABS3 (3 * SLAB)        // Ah, Al, Bh
#define SMEM_DYN (2 * SLABS3 + 4 * 512 + 1024)

__global__ __launch_bounds__(512, 2) void k_dist() {
    int bi = blockIdx.y, bj = blockIdx.x;
    if (bj < bi) return;

    extern __shared__ uint8_t dyn_smem[];
    uintptr_t base = ((uintptr_t)dyn_smem + 1023) & ~(uintptr_t)1023;
    uint8_t* slab = (uint8_t*)base;                       // 2 buffers x 3 slabs
    float* sNi = (float*)(base + 2 * SLABS3);
    float* sNj = (float*)(base + 2 * SLABS3 + 512);
    float* sRow = (float*)(base + 2 * SLABS3 + 1024);
    float* sCol = (float*)(base + 2 * SLABS3 + 1536);

    int t = threadIdx.x;
    int lid = t & 31, w = t >> 5;
    int warp_m = w & 3, warp_n = w >> 2;
    int m_base = warp_m * 32, n_base = warp_n * 32;
    int i0 = bi * 128, j0 = bj * 128;
    bool diag = (bi == bj);

    if (t < 128) { sNi[t] = g_n2[i0 + t]; sRow[t] = 0.0f; sCol[t] = 0.0f; }
    else if (t < 256) sNj[t - 128] = g_n2[j0 + t - 128];

    const uint8_t* gh = (const uint8_t*)g_hi;
    const uint8_t* gl = (const uint8_t*)g_lo;
    uint32_t slab_s = smem_u32(slab);

    // per-thread copy mapping: 6 x 16B per chunk (2 per slab), swizzled dst
    int crow = t >> 3, cq = t & 7;
    uint32_t sw_lo = sw128((uint32_t)(crow * 128 + cq * 16));  // same for row, row+64 (bit13 untouched... recompute below)
    auto load_chunk = [&](int kb, int buf) {
        uint32_t dst0 = slab_s + buf * SLABS3;
        #pragma unroll
        for (int s = 0; s < 3; ++s) {
            const uint8_t* src = (s == 1) ? gl : gh;     // Ah, Al, Bh
            int rbase = (s < 2) ? i0 : j0;
            #pragma unroll
            for (int it = 0; it < 2; ++it) {
                int row = crow + it * 64;
                const uint8_t* gp = src + (size_t)(rbase + row) * 512
                                  + (size_t)kb * 128 + (size_t)cq * 16;
                // +64 rows = +8192 B: swizzle bits unaffected (XOR uses bits 4..9)
                uint32_t doff = dst0 + (uint32_t)(s * SLAB + it * 64 * 128) + sw_lo;
                CP_ASYNC16(doff, gp);
            }
        }
    };

    // logical (pre-swizzle) ldmatrix lane offsets within a slab
    uint32_t aOff = (uint32_t)((m_base + (lid & 15)) * 128 + ((lid >> 4) << 4));
    uint32_t bOff = (uint32_t)((n_base + (lid & 7) + ((lid >> 4) << 3)) * 128
                               + (((lid >> 3) & 1) << 4));

    float acc[2][4][4];
    #pragma unroll
    for (int mt = 0; mt < 2; ++mt)
        #pragma unroll
        for (int nt = 0; nt < 4; ++nt)
            #pragma unroll
            for (int e = 0; e < 4; ++e) acc[mt][nt][e] = 0.0f;

    load_chunk(0, 0);
    CP_COMMIT();

    for (int kb = 0; kb < 4; ++kb) {
        CP_WAIT0();
        __syncthreads();
        if (kb < 3) { load_chunk(kb + 1, (kb + 1) & 1); CP_COMMIT(); }

        uint32_t b0 = slab_s + (kb & 1) * SLABS3;
        uint32_t sAh = b0, sAl = b0 + SLAB, sBh = b0 + 2 * SLAB;

        #pragma unroll
        for (int ks = 0; ks < 4; ++ks) {
            uint32_t kofs = ks * 32;
            // swizzled addresses (+16 rows = +2048 B leaves XOR field unchanged)
            uint32_t aS = sw128(aOff + kofs);
            uint32_t bS = sw128(bOff + kofs);
            uint32_t ah0[4], ah1[4], al0[4], al1[4], bh[2][4];
            ldsm_x4(sAh + aS, ah0);
            ldsm_x4(sAh + aS + 16 * 128, ah1);
            ldsm_x4(sAl + aS, al0);
            ldsm_x4(sAl + aS + 16 * 128, al1);
            ldsm_x4(sBh + bS, bh[0]);
            ldsm_x4(sBh + bS + 16 * 128, bh[1]);
            #pragma unroll
            for (int mt = 0; mt < 2; ++mt) {
                const uint32_t* Ah = mt ? ah1 : ah0;
                const uint32_t* Al = mt ? al1 : al0;
                #pragma unroll
                for (int nh = 0; nh < 2; ++nh)
                    #pragma unroll
                    for (int sb = 0; sb < 2; ++sb) {
                        float* c = acc[mt][nh * 2 + sb];
                        mma16816(c, Ah, &bh[nh][sb * 2]);   // hi*hi
                        mma16816(c, Al, &bh[nh][sb * 2]);   // lo*hi
                    }
            }
        }
        __syncthreads();
    }

    // ---------------- epilogue ----------------
    float rmax[2][2];
    float cmax[4][2];
    #pragma unroll
    for (int a = 0; a < 2; ++a) { rmax[a][0] = 0.0f; rmax[a][1] = 0.0f; }
    #pragma unroll
    for (int a = 0; a < 4; ++a) { cmax[a][0] = 0.0f; cmax[a][1] = 0.0f; }

    #pragma unroll
    for (int mt = 0; mt < 2; ++mt) {
        int r0 = m_base + mt * 16 + (lid >> 2);
        float ni0 = sNi[r0], ni1 = sNi[r0 + 8];
        int gi0 = i0 + r0;
        #pragma unroll
        for (int nt = 0; nt < 4; ++nt) {
            int c0 = n_base + nt * 8 + (lid & 3) * 2;
            float nj0 = sNj[c0], nj1 = sNj[c0 + 1];
            int gj0 = j0 + c0;
            const float* dd = acc[mt][nt];
            float v00 = rsqrtf(fmaxf(ni0 + nj0 - 2.0f * dd[0], CLAMP_MIN));
            float v01 = rsqrtf(fmaxf(ni0 + nj1 - 2.0f * dd[1], CLAMP_MIN));
            float v10 = rsqrtf(fmaxf(ni1 + nj0 - 2.0f * dd[2], CLAMP_MIN));
            float v11 = rsqrtf(fmaxf(ni1 + nj1 - 2.0f * dd[3], CLAMP_MIN));
            if (gi0 == gj0) v00 = 0.0f;
            if (gi0 == gj0 + 1) v01 = 0.0f;
            if (gi0 + 8 == gj0) v10 = 0.0f;
            if (gi0 + 8 == gj0 + 1) v11 = 0.0f;
            rmax[mt][0] = fmaxf(rmax[mt][0], fmaxf(v00, v01));
            rmax[mt][1] = fmaxf(rmax[mt][1], fmaxf(v10, v11));
            cmax[nt][0] = fmaxf(cmax[nt][0], fmaxf(v00, v10));
            cmax[nt][1] = fmaxf(cmax[nt][1], fmaxf(v01, v11));
        }
    }

    #pragma unroll
    for (int mt = 0; mt < 2; ++mt)
        #pragma unroll
        for (int h = 0; h < 2; ++h) {
            float v = rmax[mt][h];
            v = fmaxf(v, __shfl_xor_sync(0xffffffffu, v, 1));
            v = fmaxf(v, __shfl_xor_sync(0xffffffffu, v, 2));
            if ((lid & 3) == 0)
                atomicMax((int*)&sRow[m_base + mt * 16 + h * 8 + (lid >> 2)],
                          __float_as_int(v));
        }
    if (!diag) {
        #pragma unroll
        for (int nt = 0; nt < 4; ++nt)
            #pragma unroll
            for (int e = 0; e < 2; ++e) {
                float v = cmax[nt][e];
                v = fmaxf(v, __shfl_xor_sync(0xffffffffu, v, 4));
                v = fmaxf(v, __shfl_xor_sync(0xffffffffu, v, 8));
                v = fmaxf(v, __shfl_xor_sync(0xffffffffu, v, 16));
                if (lid < 4)
                    atomicMax((int*)&sCol[n_base + nt * 8 + lid * 2 + e],
                              __float_as_int(v));
            }
    }
    __syncthreads();
    if (t < 128) {
        atomicMax((int*)&g_rowmax[i0 + t], __float_as_int(sRow[t]));
        if (!diag)
            atomicMax((int*)&g_rowmax[j0 + t], __float_as_int(sCol[t]));
    }
}

// ---------------- final mean ----------------
__global__ void k_final(float* __restrict__ out) {
    int t = threadIdx.x;
    float s = 0.0f;
    #pragma unroll 8
    for (int i = t; i < N; i += 256) s += g_rowmax[i];
    __shared__ float sm[8];
    #pragma unroll
    for (int o = 16; o; o >>= 1) s += __shfl_xor_sync(0xffffffffu, s, o);
    if ((t & 31) == 0) sm[t >> 5] = s;
    __syncthreads();
    if (t < 8) {
        float a = sm[t];
        #pragma unroll
        for (int o = 4; o; o >>= 1) a += __shfl_xor_sync(0xffu, a, o);
        if (t == 0) out[0] = a * (1.0f / (float)N);
    }
}

extern "C" void kernel_launch(void* const* d_in, const int* in_sizes, int n_in,
                              void* d_out, int out_size) {
    const float* x = (const float*)d_in[0];
    float* out = (float*)d_out;

    cudaFuncSetAttribute(k_dist, cudaFuncAttributeMaxDynamicSharedMemorySize, SMEM_DYN);

    k_init<<<32, 256>>>();
    k_normalize<<<N / 8, 256>>>(x);
    k_prep<<<N / 8, 256>>>();
    dim3 grid(64, 64);
    k_dist<<<grid, 512, SMEM_DYN>>>();
    k_final<<<1, 256>>>(out);
}

// round 8
// speedup vs baseline: 10.5092x; 1.4189x over previous
#include <cuda_runtime.h>
#include <cuda_bf16.h>
#include <math.h>
#include <stdint.h>

#define N 8192
#define D 256
#define CLAMP_MIN 1e-30f

// ---------------- device scratch (no allocations allowed) ----------------
__device__ float g_colsum[D];
__device__ float g_n2[N];                            // ||z_i||^2 after centering
__device__ float g_rowmax[N];                        // max_j 1/dist (bits monotone)
__device__ __nv_bfloat16 g_hi[(size_t)N * D];        // bf16 of centered z

__device__ __forceinline__ uint32_t smem_u32(const void* p) {
    return (uint32_t)__cvta_generic_to_shared(p);
}
__device__ __forceinline__ uint32_t sw128(uint32_t off) {
    return off ^ ((off >> 3) & 0x70);
}

// ---------------- sm_80-era building blocks (compile for plain sm_103) ----
__device__ __forceinline__ void ldsm_x4(uint32_t addr, uint32_t* r) {
    asm volatile("ldmatrix.sync.aligned.m8n8.x4.shared.b16 {%0,%1,%2,%3}, [%4];"
                 : "=r"(r[0]), "=r"(r[1]), "=r"(r[2]), "=r"(r[3]) : "r"(addr));
}
__device__ __forceinline__ void mma16816(float* c, const uint32_t* a, const uint32_t* b) {
    asm volatile(
        "mma.sync.aligned.m16n8k16.row.col.f32.bf16.bf16.f32 "
        "{%0,%1,%2,%3}, {%4,%5,%6,%7}, {%8,%9}, {%0,%1,%2,%3};"
        : "+f"(c[0]), "+f"(c[1]), "+f"(c[2]), "+f"(c[3])
        : "r"(a[0]), "r"(a[1]), "r"(a[2]), "r"(a[3]), "r"(b[0]), "r"(b[1]));
}
#define CP_ASYNC16(dst, src) \
    asm volatile("cp.async.cg.shared.global [%0], [%1], 16;" :: "r"(dst), "l"(src))
#define CP_COMMIT() asm volatile("cp.async.commit_group;" ::: "memory")
#define CP_WAIT0()  asm volatile("cp.async.wait_group 0;" ::: "memory")

// ---------------- init: zero accumulators ----------------
__global__ void k_init() {
    int idx = blockIdx.x * 256 + threadIdx.x;
    if (idx < N) g_rowmax[idx] = 0.0f;
    if (idx < D) g_colsum[idx] = 0.0f;
}

// ---------------- column sums of row-normalized x (no g_y write) ----------
__global__ __launch_bounds__(256) void k_colsum(const float* __restrict__ x) {
    __shared__ float scol[8][256];
    int w = threadIdx.x >> 5, lane = threadIdx.x & 31;
    int row = blockIdx.x * 8 + w;
    const float4* x4 = (const float4*)(x + (size_t)row * D);
    float4 a = x4[lane * 2], b = x4[lane * 2 + 1];
    float s = a.x * a.x + a.y * a.y + a.z * a.z + a.w * a.w
            + b.x * b.x + b.y * b.y + b.z * b.z + b.w * b.w;
    #pragma unroll
    for (int o = 16; o; o >>= 1) s += __shfl_xor_sync(0xffffffffu, s, o);
    float inv = 1.0f / sqrtf(s);
    a.x *= inv; a.y *= inv; a.z *= inv; a.w *= inv;
    b.x *= inv; b.y *= inv; b.z *= inv; b.w *= inv;
    ((float4*)scol[w])[lane * 2] = a;
    ((float4*)scol[w])[lane * 2 + 1] = b;
    __syncthreads();
    int t = threadIdx.x;
    float cs = scol[0][t];
    #pragma unroll
    for (int r = 1; r < 8; ++r) cs += scol[r][t];
    atomicAdd(&g_colsum[t], cs);
}

// ---------------- normalize + center + n2 + bf16: warp per row ------------
__global__ __launch_bounds__(256) void k_prep(const float* __restrict__ x) {
    int w = threadIdx.x >> 5, lane = threadIdx.x & 31;
    int row = blockIdx.x * 8 + w;
    const float4* x4 = (const float4*)(x + (size_t)row * D);
    const float4* c4 = (const float4*)g_colsum;
    float4 a = x4[lane * 2], b = x4[lane * 2 + 1];
    float s = a.x * a.x + a.y * a.y + a.z * a.z + a.w * a.w
            + b.x * b.x + b.y * b.y + b.z * b.z + b.w * b.w;
    #pragma unroll
    for (int o = 16; o; o >>= 1) s += __shfl_xor_sync(0xffffffffu, s, o);
    float inv = 1.0f / sqrtf(s);   // identical ops to k_colsum -> same values
    float z[8];
    {
        float4 ca = c4[lane * 2], cb = c4[lane * 2 + 1];
        const float invn = 1.0f / (float)N;
        z[0] = a.x * inv - ca.x * invn; z[1] = a.y * inv - ca.y * invn;
        z[2] = a.z * inv - ca.z * invn; z[3] = a.w * inv - ca.w * invn;
        z[4] = b.x * inv - cb.x * invn; z[5] = b.y * inv - cb.y * invn;
        z[6] = b.z * inv - cb.z * invn; z[7] = b.w * inv - cb.w * invn;
    }
    float n2 = 0.0f;
    unsigned short hb[8];
    #pragma unroll
    for (int e = 0; e < 8; ++e) {
        n2 += z[e] * z[e];
        __nv_bfloat16 h = __float2bfloat16_rn(z[e]);
        hb[e] = *(unsigned short*)&h;
    }
    #pragma unroll
    for (int o = 16; o; o >>= 1) n2 += __shfl_xor_sync(0xffffffffu, n2, o);
    if (lane == 0) g_n2[row] = n2;
    uint4 hv;
    hv.x = (uint32_t)hb[0] | ((uint32_t)hb[1] << 16);
    hv.y = (uint32_t)hb[2] | ((uint32_t)hb[3] << 16);
    hv.z = (uint32_t)hb[4] | ((uint32_t)hb[5] << 16);
    hv.w = (uint32_t)hb[6] | ((uint32_t)hb[7] << 16);
    ((uint4*)(g_hi + (size_t)row * D))[lane] = hv;
}

// ---------------- fused mma.sync Gram + distance + row/col max ----------------
// 128x128 tile per CTA (upper triangle, 1D triangular grid of 2080 blocks),
// 512 threads = 4x4 warp grid, pure-bf16 Gram (hi*hi only).
// 128B smem rows + SW128 swizzle; K chunks of 64, double-buffered cp.async.
#define SLAB (128 * 128)         // 16384 B per slab
#define SLABS2 (2 * SLAB)        // Ah, Bh
#define SMEM_DYN (2 * SLABS2 + 4 * 512 + 1024)

__global__ __launch_bounds__(512, 2) void k_dist() {
    // decode upper-triangular (bi, bj) from linear block id
    int u = blockIdx.x;
    int bi = (int)(64.5f - sqrtf(fmaxf(64.5f * 64.5f - 2.0f * (float)u, 0.0f)));
    while (bi * 64 - (bi * (bi - 1)) / 2 > u) --bi;
    while ((bi + 1) * 64 - ((bi + 1) * bi) / 2 <= u) ++bi;
    int bj = bi + (u - (bi * 64 - (bi * (bi - 1)) / 2));

    extern __shared__ uint8_t dyn_smem[];
    uintptr_t base = ((uintptr_t)dyn_smem + 1023) & ~(uintptr_t)1023;
    uint8_t* slab = (uint8_t*)base;                       // 2 buffers x 2 slabs
    float* sNi = (float*)(base + 2 * SLABS2);
    float* sNj = (float*)(base + 2 * SLABS2 + 512);
    float* sRow = (float*)(base + 2 * SLABS2 + 1024);
    float* sCol = (float*)(base + 2 * SLABS2 + 1536);

    int t = threadIdx.x;
    int lid = t & 31, w = t >> 5;
    int warp_m = w & 3, warp_n = w >> 2;
    int m_base = warp_m * 32, n_base = warp_n * 32;
    int i0 = bi * 128, j0 = bj * 128;
    bool diag = (bi == bj);

    if (t < 128) { sNi[t] = g_n2[i0 + t]; sRow[t] = 0.0f; sCol[t] = 0.0f; }
    else if (t < 256) sNj[t - 128] = g_n2[j0 + t - 128];

    const uint8_t* gh = (const uint8_t*)g_hi;
    uint32_t slab_s = smem_u32(slab);

    // per-thread copy mapping: 4 x 16B per chunk (2 per slab), swizzled dst
    int crow = t >> 3, cq = t & 7;
    uint32_t sw_lo = sw128((uint32_t)(crow * 128 + cq * 16));
    auto load_chunk = [&](int kb, int buf) {
        uint32_t dst0 = slab_s + buf * SLABS2;
        #pragma unroll
        for (int s = 0; s < 2; ++s) {
            int rbase = (s == 0) ? i0 : j0;
            #pragma unroll
            for (int it = 0; it < 2; ++it) {
                int row = crow + it * 64;
                const uint8_t* gp = gh + (size_t)(rbase + row) * 512
                                  + (size_t)kb * 128 + (size_t)cq * 16;
                // +64 rows = +8192 B leaves the XOR field untouched
                uint32_t doff = dst0 + (uint32_t)(s * SLAB + it * 64 * 128) + sw_lo;
                CP_ASYNC16(doff, gp);
            }
        }
    };

    // swizzled ldmatrix base addresses; per-ks offset is a pure XOR
    uint32_t aSw = sw128((uint32_t)((m_base + (lid & 15)) * 128 + ((lid >> 4) << 4)));
    uint32_t bSw = sw128((uint32_t)((n_base + (lid & 7) + ((lid >> 4) << 3)) * 128
                                    + (((lid >> 3) & 1) << 4)));

    float acc[2][4][4];
    #pragma unroll
    for (int mt = 0; mt < 2; ++mt)
        #pragma unroll
        for (int nt = 0; nt < 4; ++nt)
            #pragma unroll
            for (int e = 0; e < 4; ++e) acc[mt][nt][e] = 0.0f;

    load_chunk(0, 0);
    CP_COMMIT();

    for (int kb = 0; kb < 4; ++kb) {
        CP_WAIT0();
        __syncthreads();   // single barrier: orders buffer reuse + copy visibility
        if (kb < 3) { load_chunk(kb + 1, (kb + 1) & 1); CP_COMMIT(); }

        uint32_t b0 = slab_s + (kb & 1) * SLABS2;
        uint32_t sAh = b0, sBh = b0 + SLAB;

        #pragma unroll
        for (int ks = 0; ks < 4; ++ks) {
            uint32_t kofs = ks * 32;           // bits 5-6: disjoint from XOR field
            uint32_t aS = aSw ^ kofs;
            uint32_t bS = bSw ^ kofs;
            uint32_t ah0[4], ah1[4], bh[2][4];
            ldsm_x4(sAh + aS, ah0);
            ldsm_x4(sAh + aS + 16 * 128, ah1);
            ldsm_x4(sBh + bS, bh[0]);
            ldsm_x4(sBh + bS + 16 * 128, bh[1]);
            #pragma unroll
            for (int mt = 0; mt < 2; ++mt) {
                const uint32_t* Ah = mt ? ah1 : ah0;
                #pragma unroll
                for (int nh = 0; nh < 2; ++nh)
                    #pragma unroll
                    for (int sb = 0; sb < 2; ++sb)
                        mma16816(acc[mt][nh * 2 + sb], Ah, &bh[nh][sb * 2]);
            }
        }
    }
    __syncthreads();

    // ---------------- epilogue ----------------
    float rmax[2][2];
    float cmax[4][2];
    #pragma unroll
    for (int a = 0; a < 2; ++a) { rmax[a][0] = 0.0f; rmax[a][1] = 0.0f; }
    #pragma unroll
    for (int a = 0; a < 4; ++a) { cmax[a][0] = 0.0f; cmax[a][1] = 0.0f; }

    #pragma unroll
    for (int mt = 0; mt < 2; ++mt) {
        int r0 = m_base + mt * 16 + (lid >> 2);
        float ni0 = sNi[r0], ni1 = sNi[r0 + 8];
        int gi0 = i0 + r0;
        #pragma unroll
        for (int nt = 0; nt < 4; ++nt) {
            int c0 = n_base + nt * 8 + (lid & 3) * 2;
            float nj0 = sNj[c0], nj1 = sNj[c0 + 1];
            int gj0 = j0 + c0;
            const float* dd = acc[mt][nt];
            float v00 = rsqrtf(fmaxf(ni0 + nj0 - 2.0f * dd[0], CLAMP_MIN));
            float v01 = rsqrtf(fmaxf(ni0 + nj1 - 2.0f * dd[1], CLAMP_MIN));
            float v10 = rsqrtf(fmaxf(ni1 + nj0 - 2.0f * dd[2], CLAMP_MIN));
            float v11 = rsqrtf(fmaxf(ni1 + nj1 - 2.0f * dd[3], CLAMP_MIN));
            if (gi0 == gj0) v00 = 0.0f;          // diagonal never a row max
            if (gi0 == gj0 + 1) v01 = 0.0f;
            if (gi0 + 8 == gj0) v10 = 0.0f;
            if (gi0 + 8 == gj0 + 1) v11 = 0.0f;
            rmax[mt][0] = fmaxf(rmax[mt][0], fmaxf(v00, v01));
            rmax[mt][1] = fmaxf(rmax[mt][1], fmaxf(v10, v11));
            cmax[nt][0] = fmaxf(cmax[nt][0], fmaxf(v00, v10));
            cmax[nt][1] = fmaxf(cmax[nt][1], fmaxf(v01, v11));
        }
    }

    #pragma unroll
    for (int mt = 0; mt < 2; ++mt)
        #pragma unroll
        for (int h = 0; h < 2; ++h) {
            float v = rmax[mt][h];
            v = fmaxf(v, __shfl_xor_sync(0xffffffffu, v, 1));
            v = fmaxf(v, __shfl_xor_sync(0xffffffffu, v, 2));
            if ((lid & 3) == 0)
                atomicMax((int*)&sRow[m_base + mt * 16 + h * 8 + (lid >> 2)],
                          __float_as_int(v));
        }
    if (!diag) {
        #pragma unroll
        for (int nt = 0; nt < 4; ++nt)
            #pragma unroll
            for (int e = 0; e < 2; ++e) {
                float v = cmax[nt][e];
                v = fmaxf(v, __shfl_xor_sync(0xffffffffu, v, 4));
                v = fmaxf(v, __shfl_xor_sync(0xffffffffu, v, 8));
                v = fmaxf(v, __shfl_xor_sync(0xffffffffu, v, 16));
                if (lid < 4)
                    atomicMax((int*)&sCol[n_base + nt * 8 + lid * 2 + e],
                              __float_as_int(v));
            }
    }
    __syncthreads();
    if (t < 128) {
        atomicMax((int*)&g_rowmax[i0 + t], __float_as_int(sRow[t]));
        if (!diag)
            atomicMax((int*)&g_rowmax[j0 + t], __float_as_int(sCol[t]));
    }
}

// ---------------- final mean ----------------
__global__ void k_final(float* __restrict__ out) {
    int t = threadIdx.x;
    float s = 0.0f;
    #pragma unroll 8
    for (int i = t; i < N; i += 256) s += g_rowmax[i];
    __shared__ float sm[8];
    #pragma unroll
    for (int o = 16; o; o >>= 1) s += __shfl_xor_sync(0xffffffffu, s, o);
    if ((t & 31) == 0) sm[t >> 5] = s;
    __syncthreads();
    if (t < 8) {
        float a = sm[t];
        #pragma unroll
        for (int o = 4; o; o >>= 1) a += __shfl_xor_sync(0xffu, a, o);
        if (t == 0) out[0] = a * (1.0f / (float)N);
    }
}

extern "C" void kernel_launch(void* const* d_in, const int* in_sizes, int n_in,
                              void* d_out, int out_size) {
    const float* x = (const float*)d_in[0];
    float* out = (float*)d_out;

    cudaFuncSetAttribute(k_dist, cudaFuncAttributeMaxDynamicSharedMemorySize, SMEM_DYN);

    k_init<<<32, 256>>>();
    k_colsum<<<N / 8, 256>>>(x);
    k_prep<<<N / 8, 256>>>(x);
    k_dist<<<2080, 512, SMEM_DYN>>>();
    k_final<<<1, 256>>>(out);
}

// round 13
// speedup vs baseline: 11.4446x; 1.0890x over previous
#include <cuda_runtime.h>
#include <cuda_bf16.h>
#include <math.h>
#include <stdint.h>

#define N 8192
#define D 256
#define CLAMP_MIN 1e-30f

// ---------------- device scratch (no allocations allowed) ----------------
__device__ float g_colsum[D];
__device__ float g_n2[N];                            // ||z_i||^2 after centering
__device__ float g_rowmax[N];                        // max_j 1/dist (bits monotone)
__device__ __nv_bfloat16 g_hi[(size_t)N * D];        // bf16 of centered z

__device__ __forceinline__ uint32_t smem_u32(const void* p) {
    return (uint32_t)__cvta_generic_to_shared(p);
}
__device__ __forceinline__ uint32_t sw128(uint32_t off) {
    return off ^ ((off >> 3) & 0x70);
}

// ---------------- sm_80-era building blocks (compile for plain sm_103) ----
__device__ __forceinline__ void ldsm_x4(uint32_t addr, uint32_t* r) {
    asm volatile("ldmatrix.sync.aligned.m8n8.x4.shared.b16 {%0,%1,%2,%3}, [%4];"
                 : "=r"(r[0]), "=r"(r[1]), "=r"(r[2]), "=r"(r[3]) : "r"(addr));
}
__device__ __forceinline__ void mma16816(float* c, const uint32_t* a, const uint32_t* b) {
    asm volatile(
        "mma.sync.aligned.m16n8k16.row.col.f32.bf16.bf16.f32 "
        "{%0,%1,%2,%3}, {%4,%5,%6,%7}, {%8,%9}, {%0,%1,%2,%3};"
        : "+f"(c[0]), "+f"(c[1]), "+f"(c[2]), "+f"(c[3])
        : "r"(a[0]), "r"(a[1]), "r"(a[2]), "r"(a[3]), "r"(b[0]), "r"(b[1]));
}
#define CP_ASYNC16(dst, src) \
    asm volatile("cp.async.cg.shared.global [%0], [%1], 16;" :: "r"(dst), "l"(src))
#define CP_COMMIT() asm volatile("cp.async.commit_group;" ::: "memory")
#define CP_WAIT0()  asm volatile("cp.async.wait_group 0;" ::: "memory")

// ---------------- init: zero accumulators ----------------
__global__ void k_init() {
    int idx = blockIdx.x * 256 + threadIdx.x;
    if (idx < N) g_rowmax[idx] = 0.0f;
    if (idx < D) g_colsum[idx] = 0.0f;
}

// ---------------- column sums of row-normalized x ----------
__global__ __launch_bounds__(256) void k_colsum(const float* __restrict__ x) {
    __shared__ float scol[8][256];
    int w = threadIdx.x >> 5, lane = threadIdx.x & 31;
    int row = blockIdx.x * 8 + w;
    const float4* x4 = (const float4*)(x + (size_t)row * D);
    float4 a = x4[lane * 2], b = x4[lane * 2 + 1];
    float s = a.x * a.x + a.y * a.y + a.z * a.z + a.w * a.w
            + b.x * b.x + b.y * b.y + b.z * b.z + b.w * b.w;
    #pragma unroll
    for (int o = 16; o; o >>= 1) s += __shfl_xor_sync(0xffffffffu, s, o);
    float inv = 1.0f / sqrtf(s);
    a.x *= inv; a.y *= inv; a.z *= inv; a.w *= inv;
    b.x *= inv; b.y *= inv; b.z *= inv; b.w *= inv;
    ((float4*)scol[w])[lane * 2] = a;
    ((float4*)scol[w])[lane * 2 + 1] = b;
    __syncthreads();
    int t = threadIdx.x;
    float cs = scol[0][t];
    #pragma unroll
    for (int r = 1; r < 8; ++r) cs += scol[r][t];
    atomicAdd(&g_colsum[t], cs);
}

// ---------------- normalize + center + n2 + bf16: warp per row ------------
__global__ __launch_bounds__(256) void k_prep(const float* __restrict__ x) {
    int w = threadIdx.x >> 5, lane = threadIdx.x & 31;
    int row = blockIdx.x * 8 + w;
    const float4* x4 = (const float4*)(x + (size_t)row * D);
    const float4* c4 = (const float4*)g_colsum;
    float4 a = x4[lane * 2], b = x4[lane * 2 + 1];
    float s = a.x * a.x + a.y * a.y + a.z * a.z + a.w * a.w
            + b.x * b.x + b.y * b.y + b.z * b.z + b.w * b.w;
    #pragma unroll
    for (int o = 16; o; o >>= 1) s += __shfl_xor_sync(0xffffffffu, s, o);
    float inv = 1.0f / sqrtf(s);   // identical ops to k_colsum -> same values
    float z[8];
    {
        float4 ca = c4[lane * 2], cb = c4[lane * 2 + 1];
        const float invn = 1.0f / (float)N;
        z[0] = a.x * inv - ca.x * invn; z[1] = a.y * inv - ca.y * invn;
        z[2] = a.z * inv - ca.z * invn; z[3] = a.w * inv - ca.w * invn;
        z[4] = b.x * inv - cb.x * invn; z[5] = b.y * inv - cb.y * invn;
        z[6] = b.z * inv - cb.z * invn; z[7] = b.w * inv - cb.w * invn;
    }
    float n2 = 0.0f;
    unsigned short hb[8];
    #pragma unroll
    for (int e = 0; e < 8; ++e) {
        n2 += z[e] * z[e];
        __nv_bfloat16 h = __float2bfloat16_rn(z[e]);
        hb[e] = *(unsigned short*)&h;
    }
    #pragma unroll
    for (int o = 16; o; o >>= 1) n2 += __shfl_xor_sync(0xffffffffu, n2, o);
    if (lane == 0) g_n2[row] = n2;
    uint4 hv;
    hv.x = (uint32_t)hb[0] | ((uint32_t)hb[1] << 16);
    hv.y = (uint32_t)hb[2] | ((uint32_t)hb[3] << 16);
    hv.z = (uint32_t)hb[4] | ((uint32_t)hb[5] << 16);
    hv.w = (uint32_t)hb[6] | ((uint32_t)hb[7] << 16);
    ((uint4*)(g_hi + (size_t)row * D))[lane] = hv;
}

// ---------------- fused mma.sync Gram + distance + row/col max ----------------
// 128x128 tile per CTA (upper triangle, 1D triangular grid of 2080 blocks),
// 256 threads = 2x4 warp grid, 64x32 warp tiles, pure-bf16 Gram.
// 128B smem rows + SW128 swizzle; K chunks of 64, double-buffered cp.async.
#define SLAB (128 * 128)         // 16384 B per slab
#define SLABS2 (2 * SLAB)        // Ah, Bh
#define SMEM_DYN (2 * SLABS2 + 4 * 512 + 1024)

__global__ __launch_bounds__(256, 2) void k_dist() {
    // decode upper-triangular (bi, bj) from linear block id
    int u = blockIdx.x;
    int bi = (int)(64.5f - sqrtf(fmaxf(64.5f * 64.5f - 2.0f * (float)u, 0.0f)));
    while (bi * 64 - (bi * (bi - 1)) / 2 > u) --bi;
    while ((bi + 1) * 64 - ((bi + 1) * bi) / 2 <= u) ++bi;
    int bj = bi + (u - (bi * 64 - (bi * (bi - 1)) / 2));

    extern __shared__ uint8_t dyn_smem[];
    uintptr_t base = ((uintptr_t)dyn_smem + 1023) & ~(uintptr_t)1023;
    uint8_t* slab = (uint8_t*)base;                       // 2 buffers x 2 slabs
    float* sNi = (float*)(base + 2 * SLABS2);
    float* sNj = (float*)(base + 2 * SLABS2 + 512);
    float* sRow = (float*)(base + 2 * SLABS2 + 1024);
    float* sCol = (float*)(base + 2 * SLABS2 + 1536);

    int t = threadIdx.x;
    int lid = t & 31, w = t >> 5;
    int warp_m = w >> 2, warp_n = w & 3;       // 2 x 4 warp grid
    int m_base = warp_m * 64, n_base = warp_n * 32;
    int i0 = bi * 128, j0 = bj * 128;
    bool diag = (bi == bj);

    if (t < 128) { sNi[t] = g_n2[i0 + t]; sRow[t] = 0.0f; sCol[t] = 0.0f; }
    else         sNj[t - 128] = g_n2[j0 + t - 128];

    const uint8_t* gh = (const uint8_t*)g_hi;
    uint32_t slab_s = smem_u32(slab);

    // per-thread copy mapping: 8 x 16B per chunk (4 per slab), swizzled dst
    int crow = t >> 3, cq = t & 7;             // rows 0..31, granule 0..7
    uint32_t sw_lo = sw128((uint32_t)(crow * 128 + cq * 16));
    auto load_chunk = [&](int kb, int buf) {
        uint32_t dst0 = slab_s + buf * SLABS2;
        #pragma unroll
        for (int s = 0; s < 2; ++s) {
            int rbase = (s == 0) ? i0 : j0;
            #pragma unroll
            for (int it = 0; it < 4; ++it) {
                int row = crow + it * 32;
                const uint8_t* gp = gh + (size_t)(rbase + row) * 512
                                  + (size_t)kb * 128 + (size_t)cq * 16;
                // +32 rows = +4096 B leaves the XOR field untouched
                uint32_t doff = dst0 + (uint32_t)(s * SLAB + it * 32 * 128) + sw_lo;
                CP_ASYNC16(doff, gp);
            }
        }
    };

    // swizzled ldmatrix base addresses; per-ks offset is a pure XOR
    uint32_t aSw = sw128((uint32_t)((m_base + (lid & 15)) * 128 + ((lid >> 4) << 4)));
    uint32_t bSw = sw128((uint32_t)((n_base + (lid & 7) + ((lid >> 4) << 3)) * 128
                                    + (((lid >> 3) & 1) << 4)));

    float acc[4][4][4];                        // [mt][nt][quad]
    #pragma unroll
    for (int mt = 0; mt < 4; ++mt)
        #pragma unroll
        for (int nt = 0; nt < 4; ++nt)
            #pragma unroll
            for (int e = 0; e < 4; ++e) acc[mt][nt][e] = 0.0f;

    load_chunk(0, 0);
    CP_COMMIT();

    for (int kb = 0; kb < 4; ++kb) {
        CP_WAIT0();
        __syncthreads();   // single barrier: orders buffer reuse + copy visibility
        if (kb < 3) { load_chunk(kb + 1, (kb + 1) & 1); CP_COMMIT(); }

        uint32_t b0 = slab_s + (kb & 1) * SLABS2;
        uint32_t sAh = b0, sBh = b0 + SLAB;

        #pragma unroll
        for (int ks = 0; ks < 4; ++ks) {
            uint32_t kofs = ks * 32;           // bits 5-6: disjoint from XOR field
            uint32_t aS = aSw ^ kofs;
            uint32_t bS = bSw ^ kofs;
            uint32_t ah[4][4], bh[2][4];
            #pragma unroll
            for (int mt = 0; mt < 4; ++mt)
                ldsm_x4(sAh + aS + mt * (16 * 128), ah[mt]);
            ldsm_x4(sBh + bS, bh[0]);
            ldsm_x4(sBh + bS + 16 * 128, bh[1]);
            #pragma unroll
            for (int mt = 0; mt < 4; ++mt)
                #pragma unroll
                for (int nh = 0; nh < 2; ++nh)
                    #pragma unroll
                    for (int sb = 0; sb < 2; ++sb)
                        mma16816(acc[mt][nh * 2 + sb], ah[mt], &bh[nh][sb * 2]);
        }
    }
    __syncthreads();

    // ---------------- epilogue ----------------
    float rmax[4][2];                          // [mt][row-half]
    float cmax[4][2];                          // [nt][col-parity]
    #pragma unroll
    for (int a = 0; a < 4; ++a) { rmax[a][0] = 0.0f; rmax[a][1] = 0.0f; }
    #pragma unroll
    for (int a = 0; a < 4; ++a) { cmax[a][0] = 0.0f; cmax[a][1] = 0.0f; }

    #pragma unroll
    for (int mt = 0; mt < 4; ++mt) {
        int r0 = m_base + mt * 16 + (lid >> 2);
        float ni0 = sNi[r0], ni1 = sNi[r0 + 8];
        int gi0 = i0 + r0;
        #pragma unroll
        for (int nt = 0; nt < 4; ++nt) {
            int c0 = n_base + nt * 8 + (lid & 3) * 2;
            float nj0 = sNj[c0], nj1 = sNj[c0 + 1];
            int gj0 = j0 + c0;
            const float* dd = acc[mt][nt];
            float v00 = rsqrtf(fmaxf(ni0 + nj0 - 2.0f * dd[0], CLAMP_MIN));
            float v01 = rsqrtf(fmaxf(ni0 + nj1 - 2.0f * dd[1], CLAMP_MIN));
            float v10 = rsqrtf(fmaxf(ni1 + nj0 - 2.0f * dd[2], CLAMP_MIN));
            float v11 = rsqrtf(fmaxf(ni1 + nj1 - 2.0f * dd[3], CLAMP_MIN));
            if (gi0 == gj0) v00 = 0.0f;          // diagonal never a row max
            if (gi0 == gj0 + 1) v01 = 0.0f;
            if (gi0 + 8 == gj0) v10 = 0.0f;
            if (gi0 + 8 == gj0 + 1) v11 = 0.0f;
            rmax[mt][0] = fmaxf(rmax[mt][0], fmaxf(v00, v01));
            rmax[mt][1] = fmaxf(rmax[mt][1], fmaxf(v10, v11));
            cmax[nt][0] = fmaxf(cmax[nt][0], fmaxf(v00, v10));
            cmax[nt][1] = fmaxf(cmax[nt][1], fmaxf(v01, v11));
        }
    }

    #pragma unroll
    for (int mt = 0; mt < 4; ++mt)
        #pragma unroll
        for (int h = 0; h < 2; ++h) {
            float v = rmax[mt][h];
            v = fmaxf(v, __shfl_xor_sync(0xffffffffu, v, 1));
            v = fmaxf(v, __shfl_xor_sync(0xffffffffu, v, 2));
            if ((lid & 3) == 0)
                atomicMax((int*)&sRow[m_base + mt * 16 + h * 8 + (lid >> 2)],
                          __float_as_int(v));
        }
    if (!diag) {
        #pragma unroll
        for (int nt = 0; nt < 4; ++nt)
            #pragma unroll
            for (int e = 0; e < 2; ++e) {
                float v = cmax[nt][e];
                v = fmaxf(v, __shfl_xor_sync(0xffffffffu, v, 4));
                v = fmaxf(v, __shfl_xor_sync(0xffffffffu, v, 8));
                v = fmaxf(v, __shfl_xor_sync(0xffffffffu, v, 16));
                if (lid < 4)
                    atomicMax((int*)&sCol[n_base + nt * 8 + lid * 2 + e],
                              __float_as_int(v));
            }
    }
    __syncthreads();
    if (t < 128) {
        atomicMax((int*)&g_rowmax[i0 + t], __float_as_int(sRow[t]));
        if (!diag)
            atomicMax((int*)&g_rowmax[j0 + t], __float_as_int(sCol[t]));
    }
}

// ---------------- final mean ----------------
__global__ void k_final(float* __restrict__ out) {
    int t = threadIdx.x;
    float s = 0.0f;
    #pragma unroll 8
    for (int i = t; i < N; i += 256) s += g_rowmax[i];
    __shared__ float sm[8];
    #pragma unroll
    for (int o = 16; o; o >>= 1) s += __shfl_xor_sync(0xffffffffu, s, o);
    if ((t & 31) == 0) sm[t >> 5] = s;
    __syncthreads();
    if (t < 8) {
        float a = sm[t];
        #pragma unroll
        for (int o = 4; o; o >>= 1) a += __shfl_xor_sync(0xffu, a, o);
        if (t == 0) out[0] = a * (1.0f / (float)N);
    }
}

extern "C" void kernel_launch(void* const* d_in, const int* in_sizes, int n_in,
                              void* d_out, int out_size) {
    const float* x = (const float*)d_in[0];
    float* out = (float*)d_out;

    cudaFuncSetAttribute(k_dist, cudaFuncAttributeMaxDynamicSharedMemorySize, SMEM_DYN);

    k_init<<<32, 256>>>();
    k_colsum<<<N / 8, 256>>>(x);
    k_prep<<<N / 8, 256>>>(x);
    k_dist<<<2080, 256, SMEM_DYN>>>();
    k_final<<<1, 256>>>(out);
}

// round 16
// speedup vs baseline: 12.4112x; 1.0845x over previous
#include <cuda_runtime.h>
#include <cuda_bf16.h>
#include <math.h>
#include <stdint.h>

#define N 8192
#define D 256
#define CLAMP_MIN 1e-30f

// ---------------- device scratch (no allocations allowed) ----------------
__device__ float g_n2[N];                            // ||hi_i||^2 (bf16-dequant)
__device__ float g_rowmax[N];                        // max_j 1/dist (bits monotone)
__device__ __nv_bfloat16 g_hi[(size_t)N * D];        // bf16 of normalized y

__device__ __forceinline__ uint32_t smem_u32(const void* p) {
    return (uint32_t)__cvta_generic_to_shared(p);
}
__device__ __forceinline__ uint32_t sw128(uint32_t off) {
    return off ^ ((off >> 3) & 0x70);
}

// ---------------- sm_80-era building blocks (compile for plain sm_103) ----
__device__ __forceinline__ void ldsm_x4(uint32_t addr, uint32_t* r) {
    asm volatile("ldmatrix.sync.aligned.m8n8.x4.shared.b16 {%0,%1,%2,%3}, [%4];"
                 : "=r"(r[0]), "=r"(r[1]), "=r"(r[2]), "=r"(r[3]) : "r"(addr));
}
__device__ __forceinline__ void mma16816(float* c, const uint32_t* a, const uint32_t* b) {
    asm volatile(
        "mma.sync.aligned.m16n8k16.row.col.f32.bf16.bf16.f32 "
        "{%0,%1,%2,%3}, {%4,%5,%6,%7}, {%8,%9}, {%0,%1,%2,%3};"
        : "+f"(c[0]), "+f"(c[1]), "+f"(c[2]), "+f"(c[3])
        : "r"(a[0]), "r"(a[1]), "r"(a[2]), "r"(a[3]), "r"(b[0]), "r"(b[1]));
}
#define CP_ASYNC16(dst, src) \
    asm volatile("cp.async.cg.shared.global [%0], [%1], 16;" :: "r"(dst), "l"(src))
#define CP_COMMIT() asm volatile("cp.async.commit_group;" ::: "memory")
#define CP_WAIT0()  asm volatile("cp.async.wait_group 0;" ::: "memory")

// ---------------- normalize + bf16 + n2(bf16) + rowmax init: warp per row --
// Centering dropped: pairwise distance is translation-invariant (reference
// subtracts the SAME adjustment from both operands).
__global__ __launch_bounds__(256) void k_prep(const float* __restrict__ x) {
    int w = threadIdx.x >> 5, lane = threadIdx.x & 31;
    int row = blockIdx.x * 8 + w;
    const float4* x4 = (const float4*)(x + (size_t)row * D);
    float4 a = x4[lane * 2], b = x4[lane * 2 + 1];
    float s = a.x * a.x + a.y * a.y + a.z * a.z + a.w * a.w
            + b.x * b.x + b.y * b.y + b.z * b.z + b.w * b.w;
    #pragma unroll
    for (int o = 16; o; o >>= 1) s += __shfl_xor_sync(0xffffffffu, s, o);
    float inv = 1.0f / sqrtf(s);
    float z[8] = { a.x * inv, a.y * inv, a.z * inv, a.w * inv,
                   b.x * inv, b.y * inv, b.z * inv, b.w * inv };
    float n2 = 0.0f;
    unsigned short hb[8];
    #pragma unroll
    for (int e = 0; e < 8; ++e) {
        __nv_bfloat16 h = __float2bfloat16_rn(z[e]);
        float hf = __bfloat162float(h);
        n2 += hf * hf;                       // n2 of the bf16-rounded vector
        hb[e] = *(unsigned short*)&h;
    }
    #pragma unroll
    for (int o = 16; o; o >>= 1) n2 += __shfl_xor_sync(0xffffffffu, n2, o);
    if (lane == 0) { g_n2[row] = n2; g_rowmax[row] = 0.0f; }
    uint4 hv;
    hv.x = (uint32_t)hb[0] | ((uint32_t)hb[1] << 16);
    hv.y = (uint32_t)hb[2] | ((uint32_t)hb[3] << 16);
    hv.z = (uint32_t)hb[4] | ((uint32_t)hb[5] << 16);
    hv.w = (uint32_t)hb[6] | ((uint32_t)hb[7] << 16);
    ((uint4*)(g_hi + (size_t)row * D))[lane] = hv;
}

// ---------------- fused mma.sync Gram + distance + row/col max ----------------
// 128x128 tile per CTA (upper triangle, 1D triangular grid of 2080 blocks),
// 256 threads = 2x4 warp grid, 64x32 warp tiles, pure-bf16 Gram.
// 128B smem rows + SW128 swizzle; K chunks of 64 double-buffered via cp.async;
// ldmatrix fragments double-buffered across k16-steps (LDSM || MMA overlap).
#define SLAB (128 * 128)         // 16384 B per slab
#define SLABS2 (2 * SLAB)        // Ah, Bh
#define SMEM_DYN (2 * SLABS2 + 4 * 512 + 1024)

__global__ __launch_bounds__(256, 2) void k_dist() {
    // decode upper-triangular (bi, bj) from linear block id
    int u = blockIdx.x;
    int bi = (int)(64.5f - sqrtf(fmaxf(64.5f * 64.5f - 2.0f * (float)u, 0.0f)));
    while (bi * 64 - (bi * (bi - 1)) / 2 > u) --bi;
    while ((bi + 1) * 64 - ((bi + 1) * bi) / 2 <= u) ++bi;
    int bj = bi + (u - (bi * 64 - (bi * (bi - 1)) / 2));

    extern __shared__ uint8_t dyn_smem[];
    uintptr_t base = ((uintptr_t)dyn_smem + 1023) & ~(uintptr_t)1023;
    uint8_t* slab = (uint8_t*)base;                       // 2 buffers x 2 slabs
    float* sNi = (float*)(base + 2 * SLABS2);
    float* sNj = (float*)(base + 2 * SLABS2 + 512);
    float* sRow = (float*)(base + 2 * SLABS2 + 1024);
    float* sCol = (float*)(base + 2 * SLABS2 + 1536);

    int t = threadIdx.x;
    int lid = t & 31, w = t >> 5;
    int warp_m = w >> 2, warp_n = w & 3;       // 2 x 4 warp grid
    int m_base = warp_m * 64, n_base = warp_n * 32;
    int i0 = bi * 128, j0 = bj * 128;
    bool diag = (bi == bj);

    if (t < 128) { sNi[t] = g_n2[i0 + t]; sRow[t] = 0.0f; sCol[t] = 0.0f; }
    else         sNj[t - 128] = g_n2[j0 + t - 128];

    const uint8_t* gh = (const uint8_t*)g_hi;
    uint32_t slab_s = smem_u32(slab);

    // per-thread copy mapping: 8 x 16B per chunk (4 per slab), swizzled dst
    int crow = t >> 3, cq = t & 7;             // rows 0..31, granule 0..7
    uint32_t sw_lo = sw128((uint32_t)(crow * 128 + cq * 16));
    auto load_chunk = [&](int kb, int buf) {
        uint32_t dst0 = slab_s + buf * SLABS2;
        #pragma unroll
        for (int s = 0; s < 2; ++s) {
            int rbase = (s == 0) ? i0 : j0;
            #pragma unroll
            for (int it = 0; it < 4; ++it) {
                int row = crow + it * 32;
                const uint8_t* gp = gh + (size_t)(rbase + row) * 512
                                  + (size_t)kb * 128 + (size_t)cq * 16;
                uint32_t doff = dst0 + (uint32_t)(s * SLAB + it * 32 * 128) + sw_lo;
                CP_ASYNC16(doff, gp);
            }
        }
    };

    // swizzled ldmatrix base addresses; per-ks offset is a pure XOR
    uint32_t aSw = sw128((uint32_t)((m_base + (lid & 15)) * 128 + ((lid >> 4) << 4)));
    uint32_t bSw = sw128((uint32_t)((n_base + (lid & 7) + ((lid >> 4) << 3)) * 128
                                    + (((lid >> 3) & 1) << 4)));

    float acc[4][4][4];                        // [mt][nt][quad]
    #pragma unroll
    for (int mt = 0; mt < 4; ++mt)
        #pragma unroll
        for (int nt = 0; nt < 4; ++nt)
            #pragma unroll
            for (int e = 0; e < 4; ++e) acc[mt][nt][e] = 0.0f;

    load_chunk(0, 0);
    CP_COMMIT();

    uint32_t ah[2][4][4], bh[2][2][4];         // double-buffered fragments

    for (int kb = 0; kb < 4; ++kb) {
        CP_WAIT0();
        __syncthreads();   // orders buffer reuse + copy visibility
        if (kb < 3) { load_chunk(kb + 1, (kb + 1) & 1); CP_COMMIT(); }

        uint32_t b0 = slab_s + (kb & 1) * SLABS2;
        uint32_t sAh = b0, sBh = b0 + SLAB;

        // prologue: fragments for ks=0
        {
            uint32_t aS = aSw, bS = bSw;
            #pragma unroll
            for (int mt = 0; mt < 4; ++mt)
                ldsm_x4(sAh + aS + mt * (16 * 128), ah[0][mt]);
            ldsm_x4(sBh + bS, bh[0][0]);
            ldsm_x4(sBh + bS + 16 * 128, bh[0][1]);
        }
        #pragma unroll
        for (int ks = 0; ks < 4; ++ks) {
            const int cur = ks & 1;
            if (ks < 3) {                       // prefetch ks+1 into other buffer
                uint32_t kofs = (uint32_t)((ks + 1) * 32);
                uint32_t aS = aSw ^ kofs, bS = bSw ^ kofs;
                #pragma unroll
                for (int mt = 0; mt < 4; ++mt)
                    ldsm_x4(sAh + aS + mt * (16 * 128), ah[cur ^ 1][mt]);
                ldsm_x4(sBh + bS, bh[cur ^ 1][0]);
                ldsm_x4(sBh + bS + 16 * 128, bh[cur ^ 1][1]);
            }
            #pragma unroll
            for (int mt = 0; mt < 4; ++mt)
                #pragma unroll
                for (int nh = 0; nh < 2; ++nh)
                    #pragma unroll
                    for (int sb = 0; sb < 2; ++sb)
                        mma16816(acc[mt][nh * 2 + sb], ah[cur][mt],
                                 &bh[cur][nh][sb * 2]);
        }
    }
    __syncthreads();

    // ---------------- epilogue ----------------
    float rmax[4][2];                          // [mt][row-half]
    float cmax[4][2];                          // [nt][col-parity]
    #pragma unroll
    for (int a = 0; a < 4; ++a) { rmax[a][0] = 0.0f; rmax[a][1] = 0.0f; }
    #pragma unroll
    for (int a = 0; a < 4; ++a) { cmax[a][0] = 0.0f; cmax[a][1] = 0.0f; }

    #pragma unroll
    for (int mt = 0; mt < 4; ++mt) {
        int r0 = m_base + mt * 16 + (lid >> 2);
        float ni0 = sNi[r0], ni1 = sNi[r0 + 8];
        int gi0 = i0 + r0;
        #pragma unroll
        for (int nt = 0; nt < 4; ++nt) {
            int c0 = n_base + nt * 8 + (lid & 3) * 2;
            float nj0 = sNj[c0], nj1 = sNj[c0 + 1];
            int gj0 = j0 + c0;
            const float* dd = acc[mt][nt];
            float v00 = rsqrtf(fmaxf(ni0 + nj0 - 2.0f * dd[0], CLAMP_MIN));
            float v01 = rsqrtf(fmaxf(ni0 + nj1 - 2.0f * dd[1], CLAMP_MIN));
            float v10 = rsqrtf(fmaxf(ni1 + nj0 - 2.0f * dd[2], CLAMP_MIN));
            float v11 = rsqrtf(fmaxf(ni1 + nj1 - 2.0f * dd[3], CLAMP_MIN));
            if (gi0 == gj0) v00 = 0.0f;          // diagonal never a row max
            if (gi0 == gj0 + 1) v01 = 0.0f;
            if (gi0 + 8 == gj0) v10 = 0.0f;
            if (gi0 + 8 == gj0 + 1) v11 = 0.0f;
            rmax[mt][0] = fmaxf(rmax[mt][0], fmaxf(v00, v01));
            rmax[mt][1] = fmaxf(rmax[mt][1], fmaxf(v10, v11));
            cmax[nt][0] = fmaxf(cmax[nt][0], fmaxf(v00, v10));
            cmax[nt][1] = fmaxf(cmax[nt][1], fmaxf(v01, v11));
        }
    }

    #pragma unroll
    for (int mt = 0; mt < 4; ++mt)
        #pragma unroll
        for (int h = 0; h < 2; ++h) {
            float v = rmax[mt][h];
            v = fmaxf(v, __shfl_xor_sync(0xffffffffu, v, 1));
            v = fmaxf(v, __shfl_xor_sync(0xffffffffu, v, 2));
            if ((lid & 3) == 0)
                atomicMax((int*)&sRow[m_base + mt * 16 + h * 8 + (lid >> 2)],
                          __float_as_int(v));
        }
    if (!diag) {
        #pragma unroll
        for (int nt = 0; nt < 4; ++nt)
            #pragma unroll
            for (int e = 0; e < 2; ++e) {
                float v = cmax[nt][e];
                v = fmaxf(v, __shfl_xor_sync(0xffffffffu, v, 4));
                v = fmaxf(v, __shfl_xor_sync(0xffffffffu, v, 8));
                v = fmaxf(v, __shfl_xor_sync(0xffffffffu, v, 16));
                if (lid < 4)
                    atomicMax((int*)&sCol[n_base + nt * 8 + lid * 2 + e],
                              __float_as_int(v));
            }
    }
    __syncthreads();
    if (t < 128) {
        atomicMax((int*)&g_rowmax[i0 + t], __float_as_int(sRow[t]));
        if (!diag)
            atomicMax((int*)&g_rowmax[j0 + t], __float_as_int(sCol[t]));
    }
}

// ---------------- final mean ----------------
__global__ void k_final(float* __restrict__ out) {
    int t = threadIdx.x;
    float s = 0.0f;
    #pragma unroll 8
    for (int i = t; i < N; i += 256) s += g_rowmax[i];
    __shared__ float sm[8];
    #pragma unroll
    for (int o = 16; o; o >>= 1) s += __shfl_xor_sync(0xffffffffu, s, o);
    if ((t & 31) == 0) sm[t >> 5] = s;
    __syncthreads();
    if (t < 8) {
        float a = sm[t];
        #pragma unroll
        for (int o = 4; o; o >>= 1) a += __shfl_xor_sync(0xffu, a, o);
        if (t == 0) out[0] = a * (1.0f / (float)N);
    }
}

extern "C" void kernel_launch(void* const* d_in, const int* in_sizes, int n_in,
                              void* d_out, int out_size) {
    const float* x = (const float*)d_in[0];
    float* out = (float*)d_out;

    cudaFuncSetAttribute(k_dist, cudaFuncAttributeMaxDynamicSharedMemorySize, SMEM_DYN);

    k_prep<<<N / 8, 256>>>(x);
    k_dist<<<2080, 256, SMEM_DYN>>>();
    k_final<<<1, 256>>>(out);
}

// round 17
// speedup vs baseline: 12.8580x; 1.0360x over previous
#include <cuda_runtime.h>
#include <cuda_bf16.h>
#include <math.h>
#include <stdint.h>

#define N 8192
#define D 256
#define CLAMP_MIN 1e-30f

// ---------------- device scratch (no allocations allowed) ----------------
__device__ float g_n2[N];                            // ||hi_i||^2 (bf16-dequant)
__device__ float g_rowmax[N];                        // max_j 1/dist (bits monotone)
__device__ __nv_bfloat16 g_hi[(size_t)N * D];        // bf16 of normalized y

__device__ __forceinline__ uint32_t smem_u32(const void* p) {
    return (uint32_t)__cvta_generic_to_shared(p);
}
__device__ __forceinline__ uint32_t sw128(uint32_t off) {
    return off ^ ((off >> 3) & 0x70);
}

// ---------------- sm_80-era building blocks (compile for plain sm_103) ----
__device__ __forceinline__ void ldsm_x4(uint32_t addr, uint32_t* r) {
    asm volatile("ldmatrix.sync.aligned.m8n8.x4.shared.b16 {%0,%1,%2,%3}, [%4];"
                 : "=r"(r[0]), "=r"(r[1]), "=r"(r[2]), "=r"(r[3]) : "r"(addr));
}
__device__ __forceinline__ void mma16816(float* c, const uint32_t* a, const uint32_t* b) {
    asm volatile(
        "mma.sync.aligned.m16n8k16.row.col.f32.bf16.bf16.f32 "
        "{%0,%1,%2,%3}, {%4,%5,%6,%7}, {%8,%9}, {%0,%1,%2,%3};"
        : "+f"(c[0]), "+f"(c[1]), "+f"(c[2]), "+f"(c[3])
        : "r"(a[0]), "r"(a[1]), "r"(a[2]), "r"(a[3]), "r"(b[0]), "r"(b[1]));
}
#define CP_ASYNC16(dst, src) \
    asm volatile("cp.async.cg.shared.global [%0], [%1], 16;" :: "r"(dst), "l"(src))
#define CP_COMMIT() asm volatile("cp.async.commit_group;" ::: "memory")
#define CP_WAIT0()  asm volatile("cp.async.wait_group 0;" ::: "memory")

// ---------------- normalize + bf16 + n2(bf16) + rowmax init: warp per row --
// Centering dropped: pairwise distance is translation-invariant.
__global__ __launch_bounds__(256) void k_prep(const float* __restrict__ x) {
    int w = threadIdx.x >> 5, lane = threadIdx.x & 31;
    int row = blockIdx.x * 8 + w;
    const float4* x4 = (const float4*)(x + (size_t)row * D);
    float4 a = x4[lane * 2], b = x4[lane * 2 + 1];
    float s = a.x * a.x + a.y * a.y + a.z * a.z + a.w * a.w
            + b.x * b.x + b.y * b.y + b.z * b.z + b.w * b.w;
    #pragma unroll
    for (int o = 16; o; o >>= 1) s += __shfl_xor_sync(0xffffffffu, s, o);
    float inv = 1.0f / sqrtf(s);
    float z[8] = { a.x * inv, a.y * inv, a.z * inv, a.w * inv,
                   b.x * inv, b.y * inv, b.z * inv, b.w * inv };
    float n2 = 0.0f;
    unsigned short hb[8];
    #pragma unroll
    for (int e = 0; e < 8; ++e) {
        __nv_bfloat16 h = __float2bfloat16_rn(z[e]);
        float hf = __bfloat162float(h);
        n2 += hf * hf;                       // n2 of the bf16-rounded vector
        hb[e] = *(unsigned short*)&h;
    }
    #pragma unroll
    for (int o = 16; o; o >>= 1) n2 += __shfl_xor_sync(0xffffffffu, n2, o);
    if (lane == 0) { g_n2[row] = n2; g_rowmax[row] = 0.0f; }
    uint4 hv;
    hv.x = (uint32_t)hb[0] | ((uint32_t)hb[1] << 16);
    hv.y = (uint32_t)hb[2] | ((uint32_t)hb[3] << 16);
    hv.z = (uint32_t)hb[4] | ((uint32_t)hb[5] << 16);
    hv.w = (uint32_t)hb[6] | ((uint32_t)hb[7] << 16);
    ((uint4*)(g_hi + (size_t)row * D))[lane] = hv;
}

// ---------------- fused mma.sync Gram + distance + row/col max ----------------
// 128x128 tile per CTA (upper triangle, 1D triangular grid of 2080 blocks),
// 128 threads = 2x2 warp grid, 64x64 warp tiles, pure-bf16 Gram.
// 128B smem rows + SW128 swizzle; K chunks of 64 double-buffered via cp.async;
// ldmatrix fragments double-buffered across k16-steps.
#define SLAB (128 * 128)         // 16384 B per slab
#define SLABS2 (2 * SLAB)        // Ah, Bh
#define SMEM_DYN (2 * SLABS2 + 4 * 512 + 1024)

__global__ __launch_bounds__(128, 2) void k_dist() {
    // decode upper-triangular (bi, bj) from linear block id
    int u = blockIdx.x;
    int bi = (int)(64.5f - sqrtf(fmaxf(64.5f * 64.5f - 2.0f * (float)u, 0.0f)));
    while (bi * 64 - (bi * (bi - 1)) / 2 > u) --bi;
    while ((bi + 1) * 64 - ((bi + 1) * bi) / 2 <= u) ++bi;
    int bj = bi + (u - (bi * 64 - (bi * (bi - 1)) / 2));

    extern __shared__ uint8_t dyn_smem[];
    uintptr_t base = ((uintptr_t)dyn_smem + 1023) & ~(uintptr_t)1023;
    uint8_t* slab = (uint8_t*)base;                       // 2 buffers x 2 slabs
    float* sNi = (float*)(base + 2 * SLABS2);
    float* sNj = (float*)(base + 2 * SLABS2 + 512);
    float* sRow = (float*)(base + 2 * SLABS2 + 1024);
    float* sCol = (float*)(base + 2 * SLABS2 + 1536);

    int t = threadIdx.x;
    int lid = t & 31, w = t >> 5;
    int warp_m = w >> 1, warp_n = w & 1;       // 2 x 2 warp grid
    int m_base = warp_m * 64, n_base = warp_n * 64;
    int i0 = bi * 128, j0 = bj * 128;
    bool diag = (bi == bj);

    if (t < 128) {
        sNi[t] = g_n2[i0 + t];
        sNj[t] = g_n2[j0 + t];
        sRow[t] = 0.0f; sCol[t] = 0.0f;
    }

    const uint8_t* gh = (const uint8_t*)g_hi;
    uint32_t slab_s = smem_u32(slab);

    // per-thread copy mapping: 16 x 16B per chunk (8 per slab), swizzled dst
    int crow = t >> 3, cq = t & 7;             // rows 0..15, granule 0..7
    uint32_t sw_lo = sw128((uint32_t)(crow * 128 + cq * 16));
    auto load_chunk = [&](int kb, int buf) {
        uint32_t dst0 = slab_s + buf * SLABS2;
        #pragma unroll
        for (int s = 0; s < 2; ++s) {
            int rbase = (s == 0) ? i0 : j0;
            #pragma unroll
            for (int it = 0; it < 8; ++it) {
                int row = crow + it * 16;
                const uint8_t* gp = gh + (size_t)(rbase + row) * 512
                                  + (size_t)kb * 128 + (size_t)cq * 16;
                // +16 rows = +2048 B leaves the XOR field untouched
                uint32_t doff = dst0 + (uint32_t)(s * SLAB + it * 16 * 128) + sw_lo;
                CP_ASYNC16(doff, gp);
            }
        }
    };

    // swizzled ldmatrix base addresses; per-ks offset is a pure XOR
    uint32_t aSw = sw128((uint32_t)((m_base + (lid & 15)) * 128 + ((lid >> 4) << 4)));
    uint32_t bSw = sw128((uint32_t)((n_base + (lid & 7) + ((lid >> 4) << 3)) * 128
                                    + (((lid >> 3) & 1) << 4)));

    float acc[4][8][4];                        // [mt][nt][quad]  64x64 warp tile
    #pragma unroll
    for (int mt = 0; mt < 4; ++mt)
        #pragma unroll
        for (int nt = 0; nt < 8; ++nt)
            #pragma unroll
            for (int e = 0; e < 4; ++e) acc[mt][nt][e] = 0.0f;

    load_chunk(0, 0);
    CP_COMMIT();

    uint32_t ah[2][4][4], bh[2][4][4];         // double-buffered fragments

    for (int kb = 0; kb < 4; ++kb) {
        CP_WAIT0();
        __syncthreads();   // orders buffer reuse + copy visibility
        if (kb < 3) { load_chunk(kb + 1, (kb + 1) & 1); CP_COMMIT(); }

        uint32_t b0 = slab_s + (kb & 1) * SLABS2;
        uint32_t sAh = b0, sBh = b0 + SLAB;

        // prologue: fragments for ks=0
        #pragma unroll
        for (int q = 0; q < 4; ++q) {
            ldsm_x4(sAh + aSw + q * (16 * 128), ah[0][q]);
            ldsm_x4(sBh + bSw + q * (16 * 128), bh[0][q]);
        }
        #pragma unroll
        for (int ks = 0; ks < 4; ++ks) {
            const int cur = ks & 1;
            if (ks < 3) {                       // prefetch ks+1 into other buffer
                uint32_t kofs = (uint32_t)((ks + 1) * 32);
                uint32_t aS = aSw ^ kofs, bS = bSw ^ kofs;
                #pragma unroll
                for (int q = 0; q < 4; ++q) {
                    ldsm_x4(sAh + aS + q * (16 * 128), ah[cur ^ 1][q]);
                    ldsm_x4(sBh + bS + q * (16 * 128), bh[cur ^ 1][q]);
                }
            }
            #pragma unroll
            for (int mt = 0; mt < 4; ++mt)
                #pragma unroll
                for (int nb = 0; nb < 4; ++nb)
                    #pragma unroll
                    for (int sb = 0; sb < 2; ++sb)
                        mma16816(acc[mt][nb * 2 + sb], ah[cur][mt],
                                 &bh[cur][nb][sb * 2]);
        }
    }
    __syncthreads();

    // ---------------- epilogue ----------------
    float rmax[4][2];                          // [mt][row-half]
    float cmax[8][2];                          // [nt][col-parity]
    #pragma unroll
    for (int a = 0; a < 4; ++a) { rmax[a][0] = 0.0f; rmax[a][1] = 0.0f; }
    #pragma unroll
    for (int a = 0; a < 8; ++a) { cmax[a][0] = 0.0f; cmax[a][1] = 0.0f; }

    #pragma unroll
    for (int mt = 0; mt < 4; ++mt) {
        int r0 = m_base + mt * 16 + (lid >> 2);
        float ni0 = sNi[r0], ni1 = sNi[r0 + 8];
        int gi0 = i0 + r0;
        #pragma unroll
        for (int nt = 0; nt < 8; ++nt) {
            int c0 = n_base + nt * 8 + (lid & 3) * 2;
            float nj0 = sNj[c0], nj1 = sNj[c0 + 1];
            int gj0 = j0 + c0;
            const float* dd = acc[mt][nt];
            float v00 = rsqrtf(fmaxf(ni0 + nj0 - 2.0f * dd[0], CLAMP_MIN));
            float v01 = rsqrtf(fmaxf(ni0 + nj1 - 2.0f * dd[1], CLAMP_MIN));
            float v10 = rsqrtf(fmaxf(ni1 + nj0 - 2.0f * dd[2], CLAMP_MIN));
            float v11 = rsqrtf(fmaxf(ni1 + nj1 - 2.0f * dd[3], CLAMP_MIN));
            if (gi0 == gj0) v00 = 0.0f;          // diagonal never a row max
            if (gi0 == gj0 + 1) v01 = 0.0f;
            if (gi0 + 8 == gj0) v10 = 0.0f;
            if (gi0 + 8 == gj0 + 1) v11 = 0.0f;
            rmax[mt][0] = fmaxf(rmax[mt][0], fmaxf(v00, v01));
            rmax[mt][1] = fmaxf(rmax[mt][1], fmaxf(v10, v11));
            cmax[nt][0] = fmaxf(cmax[nt][0], fmaxf(v00, v10));
            cmax[nt][1] = fmaxf(cmax[nt][1], fmaxf(v01, v11));
        }
    }

    #pragma unroll
    for (int mt = 0; mt < 4; ++mt)
        #pragma unroll
        for (int h = 0; h < 2; ++h) {
            float v = rmax[mt][h];
            v = fmaxf(v, __shfl_xor_sync(0xffffffffu, v, 1));
            v = fmaxf(v, __shfl_xor_sync(0xffffffffu, v, 2));
            if ((lid & 3) == 0)
                atomicMax((int*)&sRow[m_base + mt * 16 + h * 8 + (lid >> 2)],
                          __float_as_int(v));
        }
    if (!diag) {
        #pragma unroll
        for (int nt = 0; nt < 8; ++nt)
            #pragma unroll
            for (int e = 0; e < 2; ++e) {
                float v = cmax[nt][e];
                v = fmaxf(v, __shfl_xor_sync(0xffffffffu, v, 4));
                v = fmaxf(v, __shfl_xor_sync(0xffffffffu, v, 8));
                v = fmaxf(v, __shfl_xor_sync(0xffffffffu, v, 16));
                if (lid < 4)
                    atomicMax((int*)&sCol[n_base + nt * 8 + lid * 2 + e],
                              __float_as_int(v));
            }
    }
    __syncthreads();
    if (t < 128) {
        atomicMax((int*)&g_rowmax[i0 + t], __float_as_int(sRow[t]));
        if (!diag)
            atomicMax((int*)&g_rowmax[j0 + t], __float_as_int(sCol[t]));
    }
}

// ---------------- final mean ----------------
__global__ void k_final(float* __restrict__ out) {
    int t = threadIdx.x;
    float s = 0.0f;
    #pragma unroll 8
    for (int i = t; i < N; i += 256) s += g_rowmax[i];
    __shared__ float sm[8];
    #pragma unroll
    for (int o = 16; o; o >>= 1) s += __shfl_xor_sync(0xffffffffu, s, o);
    if ((t & 31) == 0) sm[t >> 5] = s;
    __syncthreads();
    if (t < 8) {
        float a = sm[t];
        #pragma unroll
        for (int o = 4; o; o >>= 1) a += __shfl_xor_sync(0xffu, a, o);
        if (t == 0) out[0] = a * (1.0f / (float)N);
    }
}

extern "C" void kernel_launch(void* const* d_in, const int* in_sizes, int n_in,
                              void* d_out, int out_size) {
    const float* x = (const float*)d_in[0];
    float* out = (float*)d_out;

    cudaFuncSetAttribute(k_dist, cudaFuncAttributeMaxDynamicSharedMemorySize, SMEM_DYN);

    k_prep<<<N / 8, 256>>>(x);
    k_dist<<<2080, 128, SMEM_DYN>>>();
    k_final<<<1, 256>>>(out);
}